// round 9
// baseline (speedup 1.0000x reference)
#include <cuda_runtime.h>
#include <cuda_bf16.h>
#include <cstdint>

// ---------------- problem constants ----------------
#define BB    16
#define H1    128
#define W1    128
#define H2    256
#define W2    256

// ---------------- scratch ----------------
__device__ __align__(16) __nv_bfloat16 g_xt[(size_t)BB * H1 * W1 * 128];   // x NHWC hi|lo
__device__ __align__(16) __nv_bfloat16 g_up[(size_t)BB * H2 * W2 * 128];   // upsampled NHWC hi|lo
__device__ __align__(16) __nv_bfloat16 g_wt1[(size_t)9 * 256 * 128];       // conv1 weights [tap][n][128]
__device__ __align__(16) __nv_bfloat16 g_wt2[(size_t)9 * 64 * 128];        // conv2 weights

// smem geometry (bytes)
#define APITCH   272
#define PATCHROW 198                               // 3 input rows x 66 cols
#define PATCH_BYTES (PATCHROW * APITCH)            // 53,856
#define BBUF_OFF PATCH_BYTES
#define STPITCH  68                                // staging pitch (floats), M=64
#define NTHREADS 256

__device__ __forceinline__ uint32_t smem_u32(const void* p) {
    uint32_t a;
    asm("{ .reg .u64 t; cvta.to.shared.u64 t, %1; cvt.u32.u64 %0, t; }" : "=r"(a) : "l"(p));
    return a;
}

#define LDSM4(r, a) \
    asm volatile("ldmatrix.sync.aligned.m8n8.x4.shared.b16 {%0,%1,%2,%3}, [%4];" \
        : "=r"((r)[0]), "=r"((r)[1]), "=r"((r)[2]), "=r"((r)[3]) : "r"(a))
#define MMA(c, a, b) \
    asm volatile("mma.sync.aligned.m16n8k16.row.col.f32.bf16.bf16.f32 " \
        "{%0,%1,%2,%3},{%4,%5,%6,%7},{%8,%9},{%0,%1,%2,%3};" \
        : "+f"((c)[0]), "+f"((c)[1]), "+f"((c)[2]), "+f"((c)[3]) \
        : "r"((a)[0]), "r"((a)[1]), "r"((a)[2]), "r"((a)[3]), "r"((b)[0]), "r"((b)[1]))
#define CPASYNC(dst, src) \
    asm volatile("cp.async.cg.shared.global [%0], [%1], 16;" :: "r"(dst), "l"(src))
#define CPASYNC_Z(dst, src, sz) \
    asm volatile("cp.async.cg.shared.global [%0], [%1], 16, %2;" :: "r"(dst), "l"(src), "r"(sz))
#define CPCOMMIT() asm volatile("cp.async.commit_group;")

union BF8 { __nv_bfloat16 h[8]; uint4 v; };

// ---------------- prep: x NCHW fp32 -> NHWC [hi(64)|lo(64)] bf16 ----------------
__global__ void prep_x(const float* __restrict__ x, __nv_bfloat16* __restrict__ xt) {
    __shared__ float s[64][33];
    int lane = threadIdx.x & 31, ty = threadIdx.x >> 5;
    int w0 = blockIdx.x * 32, h = blockIdx.y, b = blockIdx.z;
    #pragma unroll
    for (int i = 0; i < 8; i++) {
        int ci = i * 8 + ty;
        s[ci][lane] = x[(((size_t)b * 64 + ci) * H1 + h) * W1 + w0 + lane];
    }
    __syncthreads();
    int wp = threadIdx.x >> 3, seg = threadIdx.x & 7;
    BF8 hi, lo;
    #pragma unroll
    for (int j = 0; j < 8; j++) {
        float v = s[seg * 8 + j][wp];
        __nv_bfloat16 hb = __float2bfloat16(v);
        hi.h[j] = hb;
        lo.h[j] = __float2bfloat16(v - __bfloat162float(hb));
    }
    size_t base = (((size_t)b * H1 + h) * W1 + (w0 + wp)) * 128;
    *(uint4*)&xt[base + seg * 8]      = hi.v;
    *(uint4*)&xt[base + 64 + seg * 8] = lo.v;
}

// ---------------- prep: weights OIHW -> [tap][n][hi64|lo64] ----------------
__global__ void prep_w(const float* __restrict__ w, __nv_bfloat16* __restrict__ wt,
                       int NT, int conv1) {
    int idx = blockIdx.x * 256 + threadIdx.x;
    if (idx >= 9 * NT * 64) return;
    int ci = idx & 63;
    int rem = idx >> 6;
    int n = rem % NT, tap = rem / NT;
    int oc;
    if (conv1) {
        int cch = n >> 7, nl = n & 127;
        oc = ((nl >> 5) << 6) + (cch << 5) + (nl & 31);
    } else oc = n;
    float v = w[((size_t)oc * 64 + ci) * 9 + tap];
    __nv_bfloat16 hb = __float2bfloat16(v);
    wt[((size_t)tap * NT + n) * 128 + ci]      = hb;
    wt[((size_t)tap * NT + n) * 128 + 64 + ci] = __float2bfloat16(v - __bfloat162float(hb));
}

// ---------------- implicit-GEMM conv via mma.sync, M=64, 256 thr, 2 CTAs/SM ----------------
template<int NTILES, bool CONV1>
__global__ void __launch_bounds__(NTHREADS, 2)
gemm_conv(const __nv_bfloat16* __restrict__ xin,
          const __nv_bfloat16* __restrict__ wt,
          const float* __restrict__ bias,
          float* __restrict__ out,            // conv2 only
          __nv_bfloat16* __restrict__ up)     // conv1 only
{
    constexpr int MTILES = 2;
    constexpr int NT     = NTILES * 8 * 4;    // 128 (conv1) or 64 (conv2)
    constexpr int NTOT   = CONV1 ? 256 : 64;
    const int Hin = CONV1 ? H1 : H2;
    const int Win = CONV1 ? W1 : W2;
    const int colTiles = Win / 64;

    extern __shared__ __align__(16) char smem[];
    const uint32_t sb = smem_u32(smem);
    const int tid = threadIdx.x, wid = tid >> 5, lane = tid & 31;
    const int wm = wid >> 2, wn = wid & 3;       // 2 x 4 warp grid

    const int twi = (int)blockIdx.x % colTiles;
    const int cch = (int)blockIdx.x / colTiles;  // conv1 n-split (0/1); conv2: 0
    const int w0  = twi * 64;
    const int h0  = blockIdx.y;                  // one output row
    const int b   = blockIdx.z;
    const int nbase_g = cch * NT;

    // ---- A patch: 3 rows x 66 cols x 256B, cp.async zero-fill (no commit yet) ----
    for (int i = tid; i < PATCHROW * 16; i += NTHREADS) {
        int row = i >> 4, c16 = i & 15;
        int hh = row / 66, ww = row - hh * 66;
        int gh = h0 - 1 + hh, gw = w0 - 1 + ww;
        bool ok = (gh >= 0 && gh < Hin && gw >= 0 && gw < Win);
        const char* src = (const char*)xin
            + (ok ? (((size_t)(b * Hin + (ok ? gh : 0)) * Win + (ok ? gw : 0)) * 256 + c16 * 16) : 0);
        CPASYNC_Z(sb + row * APITCH + c16 * 16, src, ok ? 16 : 0);
    }

    float acc[MTILES][NTILES][4];
    #pragma unroll
    for (int mt = 0; mt < MTILES; mt++)
        #pragma unroll
        for (int nt = 0; nt < NTILES; nt++)
            #pragma unroll
            for (int q = 0; q < 4; q++) acc[mt][nt][q] = 0.0f;

    const uint32_t aLaneRow = (lane & 15);
    const uint32_t aLaneK   = (lane >> 4) * 16;
    const uint32_t bLaneRow = ((lane >> 4) * 8) + (lane & 7);
    const uint32_t bLaneK   = ((lane >> 3) & 1) * 16;

    #pragma unroll 1
    for (int tap = 0; tap < 9; tap++) {
        if (tap > 0) __syncthreads();           // compute(tap-1) done reading B buffer
        {   // load B(tap) — single buffer
            const char* wg = (const char*)wt;
            for (int i = tid; i < NT * 16; i += NTHREADS) {
                int n = i >> 4, c = i & 15;
                CPASYNC(sb + BBUF_OFF + n * APITCH + c * 16,
                        wg + (((size_t)tap * NTOT + nbase_g + n) * 256) + c * 16);
            }
            CPCOMMIT();
        }
        asm volatile("cp.async.wait_group 0;"); // B(tap) (+patch on tap 0) visible
        __syncthreads();

        const int dy = tap / 3, dx = tap % 3;
        const uint32_t aB = sb + (uint32_t)((dy * 66 + dx + wm * 32 + aLaneRow) * APITCH) + aLaneK;
        const uint32_t bB = sb + BBUF_OFF + (wn * NTILES * 8 + bLaneRow) * APITCH + bLaneK;

        #pragma unroll
        for (int ks = 0; ks < 4; ks++) {
            uint32_t aH[MTILES][4], aL[MTILES][4];
            uint32_t bH[NTILES * 2], bL[NTILES * 2];
            #pragma unroll
            for (int mt = 0; mt < MTILES; mt++) LDSM4(aH[mt], aB + mt * 16 * APITCH + ks * 32);
            #pragma unroll
            for (int p = 0; p < NTILES / 2; p++)
                LDSM4(&bH[4 * p], bB + p * 16 * APITCH + ks * 32);
            #pragma unroll
            for (int mt = 0; mt < MTILES; mt++)
                #pragma unroll
                for (int nt = 0; nt < NTILES; nt++) MMA(acc[mt][nt], aH[mt], &bH[2 * nt]);
            #pragma unroll
            for (int p = 0; p < NTILES / 2; p++)
                LDSM4(&bL[4 * p], bB + p * 16 * APITCH + 128 + ks * 32);
            #pragma unroll
            for (int mt = 0; mt < MTILES; mt++)
                #pragma unroll
                for (int nt = 0; nt < NTILES; nt++) MMA(acc[mt][nt], aH[mt], &bL[2 * nt]);
            #pragma unroll
            for (int mt = 0; mt < MTILES; mt++) LDSM4(aL[mt], aB + mt * 16 * APITCH + 128 + ks * 32);
            #pragma unroll
            for (int mt = 0; mt < MTILES; mt++)
                #pragma unroll
                for (int nt = 0; nt < NTILES; nt++) MMA(acc[mt][nt], aL[mt], &bH[2 * nt]);
        }
    }

    // ---- stage (n, m) fp32 + bias into smem (reuse patch area) ----
    __syncthreads();
    float* st = (float*)smem;
    #pragma unroll
    for (int mt = 0; mt < MTILES; mt++)
        #pragma unroll
        for (int nt = 0; nt < NTILES; nt++) {
            int nl = wn * NTILES * 8 + nt * 8 + (lane & 3) * 2;
            int m  = wm * 32 + mt * 16 + (lane >> 2);
            float bv0, bv1;
            if (CONV1) {
                int oc0 = ((nl >> 5) << 6) + (cch << 5) + (nl & 31);
                bv0 = __ldg(&bias[oc0]);
                bv1 = __ldg(&bias[oc0 + 1]);
            } else {
                bv0 = __ldg(&bias[nl]);
                bv1 = __ldg(&bias[nl + 1]);
            }
            st[(nl + 0) * STPITCH + m]     = acc[mt][nt][0] + bv0;
            st[(nl + 1) * STPITCH + m]     = acc[mt][nt][1] + bv1;
            st[(nl + 0) * STPITCH + m + 8] = acc[mt][nt][2] + bv0;
            st[(nl + 1) * STPITCH + m + 8] = acc[mt][nt][3] + bv1;
        }
    __syncthreads();

    if (CONV1) {
        // wavelet mix + bf16 hi/lo split, write upsampled NHWC. 256 items: m(64) x oct(4)
        int m = tid >> 2, oct = tid & 3;
        float vll[8], vlh[8], vhl[8], vhh[8];
        #pragma unroll
        for (int j = 0; j < 8; j++) {
            int r = oct * 8 + j;
            vll[j] = st[(r)      * STPITCH + m];
            vlh[j] = st[(r + 32) * STPITCH + m];
            vhl[j] = st[(r + 64) * STPITCH + m];
            vhh[j] = st[(r + 96) * STPITCH + m];
        }
        BF8 hi[4], lo[4];
        #pragma unroll
        for (int j = 0; j < 8; j++) {
            float ee = 0.5f * (vll[j] + vlh[j] + vhl[j] + vhh[j]);
            float eo = 0.5f * (vll[j] - vlh[j] + vhl[j] - vhh[j]);
            float oe = 0.5f * (vll[j] + vlh[j] - vhl[j] - vhh[j]);
            float oo = 0.5f * (vll[j] - vlh[j] - vhl[j] + vhh[j]);
            float q[4] = {ee, eo, oe, oo};
            #pragma unroll
            for (int p = 0; p < 4; p++) {
                __nv_bfloat16 hb = __float2bfloat16(q[p]);
                hi[p].h[j] = hb;
                lo[p].h[j] = __float2bfloat16(q[p] - __bfloat162float(hb));
            }
        }
        int ccb = cch * 32 + oct * 8;
        #pragma unroll
        for (int p = 0; p < 4; p++) {
            int dyp = p >> 1, dxp = p & 1;
            size_t px = ((size_t)(b * H2 + 2 * h0 + dyp) * W2 + 2 * (w0 + m) + dxp) * 128;
            *(uint4*)&up[px + ccb]      = hi[p].v;
            *(uint4*)&up[px + 64 + ccb] = lo[p].v;
        }
    } else {
        for (int i = tid; i < 64 * 64; i += NTHREADS) {
            int n = i >> 6, m = i & 63;
            out[((size_t)(b * 64 + n) * H2 + h0) * W2 + w0 + m] = st[n * STPITCH + m];
        }
    }
}

// ---------------- launch ----------------
extern "C" void kernel_launch(void* const* d_in, const int* in_sizes, int n_in,
                              void* d_out, int out_size)
{
    const float* x      = (const float*)d_in[0];
    const float* w_pre  = (const float*)d_in[1];
    const float* b_pre  = (const float*)d_in[2];
    const float* w_post = (const float*)d_in[3];
    const float* b_post = (const float*)d_in[4];
    float* out = (float*)d_out;

    __nv_bfloat16 *xt, *up, *wt1, *wt2;
    cudaGetSymbolAddress((void**)&xt,  g_xt);
    cudaGetSymbolAddress((void**)&up,  g_up);
    cudaGetSymbolAddress((void**)&wt1, g_wt1);
    cudaGetSymbolAddress((void**)&wt2, g_wt2);

    const int smem1 = PATCH_BYTES + 128 * APITCH;   // 88,672
    const int smem2 = PATCH_BYTES + 64 * APITCH;    // 71,264
    cudaFuncSetAttribute(gemm_conv<4, true>,  cudaFuncAttributeMaxDynamicSharedMemorySize, smem1);
    cudaFuncSetAttribute(gemm_conv<2, false>, cudaFuncAttributeMaxDynamicSharedMemorySize, smem2);

    prep_x<<<dim3(4, 128, 16), 256>>>(x, xt);
    prep_w<<<(9 * 256 * 64 + 255) / 256, 256>>>(w_pre, wt1, 256, 1);
    prep_w<<<(9 * 64 * 64 + 255) / 256, 256>>>(w_post, wt2, 64, 0);

    // conv1: 2 col-tiles * 2 n-chunks, 128 rows, 16 batches
    gemm_conv<4, true><<<dim3(4, 128, 16), NTHREADS, smem1>>>(xt, wt1, b_pre, nullptr, up);
    // conv2: 4 col-tiles, 256 rows, 16 batches
    gemm_conv<2, false><<<dim3(4, 256, 16), NTHREADS, smem2>>>(up, wt2, b_post, out, nullptr);
}

// round 11
// speedup vs baseline: 1.1238x; 1.1238x over previous
#include <cuda_runtime.h>
#include <cuda_bf16.h>
#include <cstdint>

// ---------------- problem constants ----------------
#define BB    16
#define H1    128
#define W1    128
#define H2    256
#define W2    256

// ---------------- scratch ----------------
__device__ __align__(16) __nv_bfloat16 g_xt[(size_t)BB * H1 * W1 * 128];   // x NHWC hi|lo
__device__ __align__(16) __nv_bfloat16 g_up[(size_t)BB * H2 * W2 * 128];   // upsampled NHWC hi|lo
__device__ __align__(16) __nv_bfloat16 g_wt1[(size_t)9 * 256 * 128];       // conv1 weights [tap][n][128]
__device__ __align__(16) __nv_bfloat16 g_wt2[(size_t)9 * 64 * 128];        // conv2 weights

// smem geometry (bytes)
#define APITCH   272
#define PATCHROW 520                               // 4 input rows x 130 cols
#define PATCH_BYTES (PATCHROW * APITCH)            // 141,440
#define BBUF_OFF PATCH_BYTES
#define NTHREADS 512

__device__ __forceinline__ uint32_t smem_u32(const void* p) {
    uint32_t a;
    asm("{ .reg .u64 t; cvta.to.shared.u64 t, %1; cvt.u32.u64 %0, t; }" : "=r"(a) : "l"(p));
    return a;
}

#define LDSM4(r, a) \
    asm volatile("ldmatrix.sync.aligned.m8n8.x4.shared.b16 {%0,%1,%2,%3}, [%4];" \
        : "=r"((r)[0]), "=r"((r)[1]), "=r"((r)[2]), "=r"((r)[3]) : "r"(a))
#define MMA(c, a, b) \
    asm volatile("mma.sync.aligned.m16n8k16.row.col.f32.bf16.bf16.f32 " \
        "{%0,%1,%2,%3},{%4,%5,%6,%7},{%8,%9},{%0,%1,%2,%3};" \
        : "+f"((c)[0]), "+f"((c)[1]), "+f"((c)[2]), "+f"((c)[3]) \
        : "r"((a)[0]), "r"((a)[1]), "r"((a)[2]), "r"((a)[3]), "r"((b)[0]), "r"((b)[1]))
#define CPASYNC(dst, src) \
    asm volatile("cp.async.cg.shared.global [%0], [%1], 16;" :: "r"(dst), "l"(src))
#define CPASYNC_Z(dst, src, sz) \
    asm volatile("cp.async.cg.shared.global [%0], [%1], 16, %2;" :: "r"(dst), "l"(src), "r"(sz))
#define CPCOMMIT() asm volatile("cp.async.commit_group;")

union BF8 { __nv_bfloat16 h[8]; uint4 v; };

// ---------------- prep: x NCHW fp32 -> NHWC [hi(64)|lo(64)] bf16 ----------------
__global__ void prep_x(const float* __restrict__ x, __nv_bfloat16* __restrict__ xt) {
    __shared__ float s[64][33];
    int lane = threadIdx.x & 31, ty = threadIdx.x >> 5;
    int w0 = blockIdx.x * 32, h = blockIdx.y, b = blockIdx.z;
    #pragma unroll
    for (int i = 0; i < 8; i++) {
        int ci = i * 8 + ty;
        s[ci][lane] = x[(((size_t)b * 64 + ci) * H1 + h) * W1 + w0 + lane];
    }
    __syncthreads();
    int wp = threadIdx.x >> 3, seg = threadIdx.x & 7;
    BF8 hi, lo;
    #pragma unroll
    for (int j = 0; j < 8; j++) {
        float v = s[seg * 8 + j][wp];
        __nv_bfloat16 hb = __float2bfloat16(v);
        hi.h[j] = hb;
        lo.h[j] = __float2bfloat16(v - __bfloat162float(hb));
    }
    size_t base = (((size_t)b * H1 + h) * W1 + (w0 + wp)) * 128;
    *(uint4*)&xt[base + seg * 8]      = hi.v;
    *(uint4*)&xt[base + 64 + seg * 8] = lo.v;
}

// ---------------- prep: weights OIHW -> [tap][n][hi64|lo64] ----------------
__global__ void prep_w(const float* __restrict__ w, __nv_bfloat16* __restrict__ wt,
                       int NT, int conv1) {
    int idx = blockIdx.x * 256 + threadIdx.x;
    if (idx >= 9 * NT * 64) return;
    int ci = idx & 63;
    int rem = idx >> 6;
    int n = rem % NT, tap = rem / NT;
    int oc;
    if (conv1) {
        int cch = n >> 7, nl = n & 127;
        oc = ((nl >> 5) << 6) + (cch << 5) + (nl & 31);
    } else oc = n;
    float v = w[((size_t)oc * 64 + ci) * 9 + tap];
    __nv_bfloat16 hb = __float2bfloat16(v);
    wt[((size_t)tap * NT + n) * 128 + ci]      = hb;
    wt[((size_t)tap * NT + n) * 128 + 64 + ci] = __float2bfloat16(v - __bfloat162float(hb));
}

// ---------------- implicit-GEMM conv via mma.sync, M=256 (row pair), 512 thr ----------------
// conv1: warp's 4 n-tiles = the 4 wavelet groups of channel octet wn*8 -> intra-thread mix.
template<int NTILES, bool CONV1>
__global__ void __launch_bounds__(NTHREADS)
gemm_conv(const __nv_bfloat16* __restrict__ xin,
          const __nv_bfloat16* __restrict__ wt,
          const float* __restrict__ bias,
          float* __restrict__ out,            // conv2 only
          __nv_bfloat16* __restrict__ up)     // conv1 only
{
    constexpr int MTILES = 4;
    constexpr int NT     = NTILES * 8 * 4;    // 128 (conv1) or 64 (conv2)
    constexpr int NTOT   = CONV1 ? 256 : 64;
    constexpr int BBYTES = NT * APITCH;
    const int Hin = CONV1 ? H1 : H2;
    const int Win = CONV1 ? W1 : W2;

    extern __shared__ __align__(16) char smem[];
    const uint32_t sb = smem_u32(smem);
    const int tid = threadIdx.x, wid = tid >> 5, lane = tid & 31;
    const int wm = wid >> 2, wn = wid & 3;       // 4 x 4 warp grid
    const int wrow = wm >> 1;                    // output local row 0/1
    const int wcol = (wm & 1) * 64;              // col base within row

    const int cch = CONV1 ? (int)blockIdx.x : 0;
    const int w0  = CONV1 ? 0 : (int)blockIdx.x * 128;
    const int h0  = blockIdx.y * 2;              // output row pair base
    const int b   = blockIdx.z;
    const int nbase_g = CONV1 ? cch * 128 : 0;

    // ---- A patch: 4 rows x 130 cols x 256B, cp.async zero-fill; + B(tap0); one group ----
    {
        for (int i = tid; i < PATCHROW * 16; i += NTHREADS) {
            int row = i >> 4, c16 = i & 15;
            int hh = row / 130, ww = row - hh * 130;
            int gh = h0 - 1 + hh, gw = w0 - 1 + ww;
            bool ok = (gh >= 0 && gh < Hin && gw >= 0 && gw < Win);
            const char* src = (const char*)xin
                + (ok ? (((size_t)(b * Hin + (ok ? gh : 0)) * Win + (ok ? gw : 0)) * 256 + c16 * 16) : 0);
            CPASYNC_Z(sb + row * APITCH + c16 * 16, src, ok ? 16 : 0);
        }
        const char* wg = (const char*)wt;
        for (int i = tid; i < NT * 16; i += NTHREADS) {
            int n = i >> 4, c = i & 15;
            CPASYNC(sb + BBUF_OFF + n * APITCH + c * 16,
                    wg + (((size_t)0 * NTOT + nbase_g + n) * 256) + c * 16);
        }
        CPCOMMIT();
    }

    float acc[MTILES][NTILES][4];
    #pragma unroll
    for (int mt = 0; mt < MTILES; mt++)
        #pragma unroll
        for (int nt = 0; nt < NTILES; nt++)
            #pragma unroll
            for (int q = 0; q < 4; q++) acc[mt][nt][q] = 0.0f;

    const uint32_t aLaneRow = (lane & 15);
    const uint32_t aLaneK   = (lane >> 4) * 16;
    // B x4 lane map: lane groups 0-15 / 16-31 -> two n-tiles.
    // conv1: tiles are wavelet groups at row stride 32; conv2: consecutive 8-row tiles.
    const uint32_t bLaneRow = ((lane >> 4) * (CONV1 ? 32 : 8)) + (lane & 7);
    const uint32_t bLaneK   = ((lane >> 3) & 1) * 16;
    const int bWarpBase = wn * (CONV1 ? 8 : NTILES * 8);
    const int bFetchStride = (CONV1 ? 64 : 16) * APITCH;   // rows covered per x4-pair fetch

    #pragma unroll 1
    for (int tap = 0; tap < 9; tap++) {
        asm volatile("cp.async.wait_group 0;");
        __syncthreads();                        // B(tap) visible; all warps done with buf[(tap+1)&1]
        if (tap < 8) {                          // prefetch B(tap+1), overlaps compute(tap)
            const char* wg = (const char*)wt;
            uint32_t dbuf = sb + BBUF_OFF + ((tap + 1) & 1) * BBYTES;
            for (int i = tid; i < NT * 16; i += NTHREADS) {
                int n = i >> 4, c = i & 15;
                CPASYNC(dbuf + n * APITCH + c * 16,
                        wg + (((size_t)(tap + 1) * NTOT + nbase_g + n) * 256) + c * 16);
            }
            CPCOMMIT();
        }

        const int dy = tap / 3, dx = tap % 3;
        const uint32_t aB = sb + (uint32_t)(((wrow + dy) * 130 + dx + wcol + aLaneRow) * APITCH) + aLaneK;
        const uint32_t bB = sb + BBUF_OFF + (tap & 1) * BBYTES
                          + (bWarpBase + bLaneRow) * APITCH + bLaneK;

        #pragma unroll
        for (int ks = 0; ks < 4; ks++) {
            uint32_t aH[MTILES][4], aL[MTILES][4];
            uint32_t bH[NTILES * 2], bL[NTILES * 2];   // flat: [nt][2]
            #pragma unroll
            for (int mt = 0; mt < MTILES; mt++) LDSM4(aH[mt], aB + mt * 16 * APITCH + ks * 32);
            #pragma unroll
            for (int p = 0; p < NTILES / 2; p++)
                LDSM4(&bH[4 * p], bB + p * bFetchStride + ks * 32);
            #pragma unroll
            for (int mt = 0; mt < MTILES; mt++)
                #pragma unroll
                for (int nt = 0; nt < NTILES; nt++) MMA(acc[mt][nt], aH[mt], &bH[2 * nt]);
            #pragma unroll
            for (int p = 0; p < NTILES / 2; p++)
                LDSM4(&bL[4 * p], bB + p * bFetchStride + 128 + ks * 32);
            #pragma unroll
            for (int mt = 0; mt < MTILES; mt++)
                #pragma unroll
                for (int nt = 0; nt < NTILES; nt++) MMA(acc[mt][nt], aH[mt], &bL[2 * nt]);
            #pragma unroll
            for (int mt = 0; mt < MTILES; mt++) LDSM4(aL[mt], aB + mt * 16 * APITCH + 128 + ks * 32);
            #pragma unroll
            for (int mt = 0; mt < MTILES; mt++)
                #pragma unroll
                for (int nt = 0; nt < NTILES; nt++) MMA(acc[mt][nt], aL[mt], &bH[2 * nt]);
        }
    }

    // ---- register-direct epilogues (no smem staging, no extra syncs) ----
    if (CONV1) {
        // thread fragment channels: c0, c0+1 of octet wn*8; groups = nt index.
        const int c0 = wn * 8 + (lane & 3) * 2;
        float bll[2], blh[2], bhl[2], bhh[2];
        #pragma unroll
        for (int cc = 0; cc < 2; cc++) {
            int ocb = cch * 32 + c0 + cc;
            bll[cc] = __ldg(&bias[0 * 64 + ocb]);
            blh[cc] = __ldg(&bias[1 * 64 + ocb]);
            bhl[cc] = __ldg(&bias[2 * 64 + ocb]);
            bhh[cc] = __ldg(&bias[3 * 64 + ocb]);
        }
        #pragma unroll
        for (int mt = 0; mt < MTILES; mt++) {
            #pragma unroll
            for (int sub = 0; sub < 2; sub++) {
                int m_g = wm * 64 + mt * 16 + (lane >> 2) + sub * 8;   // 0..255
                int mr = m_g >> 7, mc = m_g & 127;
                float o[4][2];
                #pragma unroll
                for (int cc = 0; cc < 2; cc++) {
                    float ll = acc[mt][0][sub * 2 + cc] + bll[cc];
                    float lh = acc[mt][1][sub * 2 + cc] + blh[cc];
                    float hl = acc[mt][2][sub * 2 + cc] + bhl[cc];
                    float hh = acc[mt][3][sub * 2 + cc] + bhh[cc];
                    o[0][cc] = 0.5f * (ll + lh + hl + hh);   // ee
                    o[1][cc] = 0.5f * (ll - lh + hl - hh);   // eo
                    o[2][cc] = 0.5f * (ll + lh - hl - hh);   // oe
                    o[3][cc] = 0.5f * (ll - lh - hl + hh);   // oo
                }
                #pragma unroll
                for (int p = 0; p < 4; p++) {
                    int dyp = p >> 1, dxp = p & 1;
                    size_t px = ((size_t)(b * H2 + 2 * (h0 / 2 * 2 + 0) + 2 * (mr) + 2 * (h0 & 1)) ) ;
                    // pixel row = 2*(h0 + mr) + dyp ; col = 2*mc + dxp
                    size_t base = (((size_t)b * H2 + 2 * (h0 + mr) + dyp) * W2 + 2 * mc + dxp) * 128
                                + cch * 32 + c0;
                    __nv_bfloat16 h0b = __float2bfloat16(o[p][0]);
                    __nv_bfloat16 h1b = __float2bfloat16(o[p][1]);
                    __nv_bfloat16 l0b = __float2bfloat16(o[p][0] - __bfloat162float(h0b));
                    __nv_bfloat16 l1b = __float2bfloat16(o[p][1] - __bfloat162float(h1b));
                    __nv_bfloat162 hv; hv.x = h0b; hv.y = h1b;
                    __nv_bfloat162 lv; lv.x = l0b; lv.y = l1b;
                    *(__nv_bfloat162*)&up[base]      = hv;
                    *(__nv_bfloat162*)&up[base + 64] = lv;
                    (void)px;
                }
            }
        }
    } else {
        #pragma unroll
        for (int mt = 0; mt < MTILES; mt++)
            #pragma unroll
            for (int nt = 0; nt < NTILES; nt++) {
                int n = wn * NTILES * 8 + nt * 8 + (lane & 3) * 2;
                float bv0 = __ldg(&bias[n]);
                float bv1 = __ldg(&bias[n + 1]);
                #pragma unroll
                for (int sub = 0; sub < 2; sub++) {
                    int m_g = wm * 64 + mt * 16 + (lane >> 2) + sub * 8;
                    size_t base = ((size_t)(b * 64 + n) * H2 + h0 + (m_g >> 7)) * W2 + w0 + (m_g & 127);
                    out[base]                       = acc[mt][nt][sub * 2 + 0] + bv0;
                    out[base + (size_t)H2 * W2]     = acc[mt][nt][sub * 2 + 1] + bv1;
                }
            }
    }
}

// ---------------- launch ----------------
extern "C" void kernel_launch(void* const* d_in, const int* in_sizes, int n_in,
                              void* d_out, int out_size)
{
    const float* x      = (const float*)d_in[0];
    const float* w_pre  = (const float*)d_in[1];
    const float* b_pre  = (const float*)d_in[2];
    const float* w_post = (const float*)d_in[3];
    const float* b_post = (const float*)d_in[4];
    float* out = (float*)d_out;

    __nv_bfloat16 *xt, *up, *wt1, *wt2;
    cudaGetSymbolAddress((void**)&xt,  g_xt);
    cudaGetSymbolAddress((void**)&up,  g_up);
    cudaGetSymbolAddress((void**)&wt1, g_wt1);
    cudaGetSymbolAddress((void**)&wt2, g_wt2);

    const int smem1 = PATCH_BYTES + 2 * 128 * APITCH;   // 211,072
    const int smem2 = PATCH_BYTES + 2 * 64 * APITCH;    // 176,256
    cudaFuncSetAttribute(gemm_conv<4, true>,  cudaFuncAttributeMaxDynamicSharedMemorySize, smem1);
    cudaFuncSetAttribute(gemm_conv<2, false>, cudaFuncAttributeMaxDynamicSharedMemorySize, smem2);

    prep_x<<<dim3(4, 128, 16), 256>>>(x, xt);
    prep_w<<<(9 * 256 * 64 + 255) / 256, 256>>>(w_pre, wt1, 256, 1);
    prep_w<<<(9 * 64 * 64 + 255) / 256, 256>>>(w_post, wt2, 64, 0);

    gemm_conv<4, true><<<dim3(2, 64, 16), NTHREADS, smem1>>>(xt, wt1, b_pre, nullptr, up);
    gemm_conv<2, false><<<dim3(2, 128, 16), NTHREADS, smem2>>>(up, wt2, b_post, out, nullptr);
}

// round 12
// speedup vs baseline: 2.5930x; 2.3073x over previous
#include <cuda_runtime.h>
#include <cuda_fp16.h>
#include <cstdint>

// ---------------- problem constants ----------------
#define BB    16
#define H1    128
#define W1    128
#define H2    256
#define W2    256

// ---------------- scratch ----------------
__device__ __align__(16) __half g_xt[(size_t)BB * H1 * W1 * 64];    // x NHWC fp16
__device__ __align__(16) __half g_up[(size_t)BB * H2 * W2 * 64];    // upsampled NHWC fp16
__device__ __align__(16) __half g_wt1[(size_t)9 * 256 * 64];        // conv1 weights [tap][n][64]
__device__ __align__(16) __half g_wt2[(size_t)9 * 64 * 64];         // conv2 weights

#define APITCH   144
#define NTHREADS 512

__device__ __forceinline__ uint32_t smem_u32(const void* p) {
    uint32_t a;
    asm("{ .reg .u64 t; cvta.to.shared.u64 t, %1; cvt.u32.u64 %0, t; }" : "=r"(a) : "l"(p));
    return a;
}

#define LDSM4(r, a) \
    asm volatile("ldmatrix.sync.aligned.m8n8.x4.shared.b16 {%0,%1,%2,%3}, [%4];" \
        : "=r"((r)[0]), "=r"((r)[1]), "=r"((r)[2]), "=r"((r)[3]) : "r"(a))
#define MMAH(c, a, b) \
    asm volatile("mma.sync.aligned.m16n8k16.row.col.f32.f16.f16.f32 " \
        "{%0,%1,%2,%3},{%4,%5,%6,%7},{%8,%9},{%0,%1,%2,%3};" \
        : "+f"((c)[0]), "+f"((c)[1]), "+f"((c)[2]), "+f"((c)[3]) \
        : "r"((a)[0]), "r"((a)[1]), "r"((a)[2]), "r"((a)[3]), "r"((b)[0]), "r"((b)[1]))
#define CPASYNC(dst, src) \
    asm volatile("cp.async.cg.shared.global [%0], [%1], 16;" :: "r"(dst), "l"(src))
#define CPASYNC_Z(dst, src, sz) \
    asm volatile("cp.async.cg.shared.global [%0], [%1], 16, %2;" :: "r"(dst), "l"(src), "r"(sz))
#define CPCOMMIT() asm volatile("cp.async.commit_group;")

union HF8 { __half h[8]; uint4 v; };

// ---------------- prep: x NCHW fp32 -> NHWC fp16 ----------------
__global__ void prep_x(const float* __restrict__ x, __half* __restrict__ xt) {
    __shared__ float s[64][33];
    int lane = threadIdx.x & 31, ty = threadIdx.x >> 5;
    int w0 = blockIdx.x * 32, h = blockIdx.y, b = blockIdx.z;
    #pragma unroll
    for (int i = 0; i < 8; i++) {
        int ci = i * 8 + ty;
        s[ci][lane] = x[(((size_t)b * 64 + ci) * H1 + h) * W1 + w0 + lane];
    }
    __syncthreads();
    int wp = threadIdx.x >> 3, seg = threadIdx.x & 7;
    HF8 v;
    #pragma unroll
    for (int j = 0; j < 8; j++) v.h[j] = __float2half_rn(s[seg * 8 + j][wp]);
    size_t base = (((size_t)b * H1 + h) * W1 + (w0 + wp)) * 64;
    *(uint4*)&xt[base + seg * 8] = v.v;
}

// ---------------- prep: weights OIHW -> [tap][n][64] fp16 ----------------
// conv1 n-order: n = cch*128 + (g*32 + cc)  ->  oc = g*64 + cch*32 + cc
__global__ void prep_w(const float* __restrict__ w, __half* __restrict__ wt,
                       int NT, int conv1) {
    int idx = blockIdx.x * 256 + threadIdx.x;
    if (idx >= 9 * NT * 64) return;
    int ci = idx & 63;
    int rem = idx >> 6;
    int n = rem % NT, tap = rem / NT;
    int oc;
    if (conv1) {
        int cch = n >> 7, nl = n & 127;
        oc = ((nl >> 5) << 6) + (cch << 5) + (nl & 31);
    } else oc = n;
    wt[((size_t)tap * NT + n) * 64 + ci] = __float2half_rn(w[((size_t)oc * 64 + ci) * 9 + tap]);
}

// ---------------- implicit-GEMM conv via fp16 mma.sync, fp32 acc ----------------
// conv1: M=256 (row pair of 128), NT=128, warps 4m x 4n.
// conv2: M=512 (row pair of 256), NT=64,  warps 8m x 2n.
template<bool CONV1>
__global__ void __launch_bounds__(NTHREADS)
gemm_conv(const __half* __restrict__ xin,
          const __half* __restrict__ wt,
          const float* __restrict__ bias,
          float* __restrict__ out,            // conv2 only
          __half* __restrict__ up)            // conv1 only
{
    constexpr int MTILES = 4, NTILES = 4;
    constexpr int NT     = CONV1 ? 128 : 64;
    constexpr int NTOT   = CONV1 ? 256 : 64;
    constexpr int PC     = CONV1 ? 130 : 258;     // patch cols (halo)
    constexpr int PROWS  = 4 * PC;                // 520 / 1032
    constexpr int BBOFF  = PROWS * APITCH;
    constexpr int BBYTES = NT * APITCH;
    constexpr int MROW   = CONV1 ? 128 : 256;     // out cols per row
    constexpr int STP    = CONV1 ? 260 : 516;     // staging pitch (floats)
    const int Hin = CONV1 ? H1 : H2;
    const int Win = CONV1 ? W1 : W2;

    extern __shared__ __align__(16) char smem[];
    const uint32_t sb = smem_u32(smem);
    const int tid = threadIdx.x, wid = tid >> 5, lane = tid & 31;
    const int wm  = CONV1 ? (wid >> 2) : (wid >> 1);
    const int wn  = CONV1 ? (wid & 3)  : (wid & 1);
    const int wmr = CONV1 ? (wm >> 1) : (wm >> 2);          // out row 0/1
    const int wmc = CONV1 ? ((wm & 1) * 64) : ((wm & 3) * 64);

    const int cch = CONV1 ? (int)blockIdx.x : 0;
    const int h0  = blockIdx.y * 2;
    const int b   = blockIdx.z;
    const int nbase_g = CONV1 ? cch * 128 : 0;

    // ---- A patch: 4 rows x PC cols x 128B, cp.async zero-fill; + B(tap0) ----
    {
        for (int i = tid; i < PROWS * 8; i += NTHREADS) {
            int row = i >> 3, c = i & 7;
            int hh = row / PC, ww = row - hh * PC;
            int gh = h0 - 1 + hh, gw = ww - 1;
            bool ok = (gh >= 0 && gh < Hin && gw >= 0 && gw < Win);
            const char* src = (const char*)xin
                + (ok ? (((size_t)(b * Hin + gh) * Win + gw) * 128 + c * 16) : 0);
            CPASYNC_Z(sb + row * APITCH + c * 16, src, ok ? 16 : 0);
        }
        const char* wg = (const char*)wt;
        for (int i = tid; i < NT * 8; i += NTHREADS) {
            int n = i >> 3, c = i & 7;
            CPASYNC(sb + BBOFF + n * APITCH + c * 16,
                    wg + ((size_t)(nbase_g + n) * 128) + c * 16);
        }
        CPCOMMIT();
    }

    float acc[MTILES][NTILES][4];
    #pragma unroll
    for (int mt = 0; mt < MTILES; mt++)
        #pragma unroll
        for (int nt = 0; nt < NTILES; nt++)
            #pragma unroll
            for (int q = 0; q < 4; q++) acc[mt][nt][q] = 0.0f;

    const uint32_t aLaneRow = (lane & 15);
    const uint32_t aLaneK   = (lane >> 4) * 16;
    const uint32_t bLaneRow = ((lane >> 4) * 8) + (lane & 7);
    const uint32_t bLaneK   = ((lane >> 3) & 1) * 16;

    #pragma unroll 1
    for (int tap = 0; tap < 9; tap++) {
        asm volatile("cp.async.wait_group 0;");
        __syncthreads();
        if (tap < 8) {                          // prefetch B(tap+1) overlapping compute(tap)
            const char* wg = (const char*)wt;
            uint32_t dbuf = sb + BBOFF + ((tap + 1) & 1) * BBYTES;
            for (int i = tid; i < NT * 8; i += NTHREADS) {
                int n = i >> 3, c = i & 7;
                CPASYNC(dbuf + n * APITCH + c * 16,
                        wg + ((size_t)((tap + 1) * NTOT + nbase_g + n) * 128) + c * 16);
            }
            CPCOMMIT();
        }

        const int dy = tap / 3, dx = tap % 3;
        const uint32_t aB = sb + (uint32_t)(((wmr + dy) * PC + dx + wmc + aLaneRow) * APITCH) + aLaneK;
        const uint32_t bB = sb + BBOFF + (tap & 1) * BBYTES + (wn * 32 + bLaneRow) * APITCH + bLaneK;

        #pragma unroll
        for (int ks = 0; ks < 4; ks++) {
            uint32_t aF[MTILES][4], bF[8];
            #pragma unroll
            for (int mt = 0; mt < MTILES; mt++) LDSM4(aF[mt], aB + mt * 16 * APITCH + ks * 32);
            #pragma unroll
            for (int p = 0; p < 2; p++) LDSM4(&bF[4 * p], bB + p * 16 * APITCH + ks * 32);
            #pragma unroll
            for (int mt = 0; mt < MTILES; mt++)
                #pragma unroll
                for (int nt = 0; nt < NTILES; nt++) MMAH(acc[mt][nt], aF[mt], &bF[2 * nt]);
        }
    }

    // ---- stage (n, m) fp32 + bias into smem (reuse patch area) ----
    __syncthreads();
    float* st = (float*)smem;
    #pragma unroll
    for (int mt = 0; mt < MTILES; mt++)
        #pragma unroll
        for (int nt = 0; nt < NTILES; nt++) {
            int nl = wn * 32 + nt * 8 + (lane & 3) * 2;
            int m  = wmr * MROW + wmc + mt * 16 + (lane >> 2);
            float bv0, bv1;
            if (CONV1) {
                int oc0 = ((nl >> 5) << 6) + (cch << 5) + (nl & 31);
                bv0 = __ldg(&bias[oc0]);
                bv1 = __ldg(&bias[oc0 + 1]);
            } else {
                bv0 = __ldg(&bias[nl]);
                bv1 = __ldg(&bias[nl + 1]);
            }
            st[(nl + 0) * STP + m]     = acc[mt][nt][0] + bv0;
            st[(nl + 1) * STP + m]     = acc[mt][nt][1] + bv1;
            st[(nl + 0) * STP + m + 8] = acc[mt][nt][2] + bv0;
            st[(nl + 1) * STP + m + 8] = acc[mt][nt][3] + bv1;
        }
    __syncthreads();

    if (CONV1) {
        // wavelet mix -> fp16 upsampled NHWC. 1024 items: m(256) x oct(4)
        #pragma unroll
        for (int it = 0; it < 2; it++) {
            int item = it * NTHREADS + tid;
            int m = item >> 2, oct = item & 3;
            int mr = m >> 7, mc = m & 127;
            float vll[8], vlh[8], vhl[8], vhh[8];
            #pragma unroll
            for (int j = 0; j < 8; j++) {
                int r = oct * 8 + j;
                vll[j] = st[(r)      * STP + m];
                vlh[j] = st[(r + 32) * STP + m];
                vhl[j] = st[(r + 64) * STP + m];
                vhh[j] = st[(r + 96) * STP + m];
            }
            HF8 q[4];
            #pragma unroll
            for (int j = 0; j < 8; j++) {
                float ee = 0.5f * (vll[j] + vlh[j] + vhl[j] + vhh[j]);
                float eo = 0.5f * (vll[j] - vlh[j] + vhl[j] - vhh[j]);
                float oe = 0.5f * (vll[j] + vlh[j] - vhl[j] - vhh[j]);
                float oo = 0.5f * (vll[j] - vlh[j] - vhl[j] + vhh[j]);
                q[0].h[j] = __float2half_rn(ee);
                q[1].h[j] = __float2half_rn(eo);
                q[2].h[j] = __float2half_rn(oe);
                q[3].h[j] = __float2half_rn(oo);
            }
            int ccb = cch * 32 + oct * 8;
            #pragma unroll
            for (int p = 0; p < 4; p++) {
                int dyp = p >> 1, dxp = p & 1;
                size_t px = (((size_t)b * H2 + 2 * (h0 + mr) + dyp) * W2 + 2 * mc + dxp) * 64;
                *(uint4*)&up[px + ccb] = q[p].v;
            }
        }
    } else {
        for (int i = tid; i < 64 * 512; i += NTHREADS) {
            int n = i >> 9, m = i & 511;
            out[((size_t)(b * 64 + n) * H2 + h0 + (m >> 8)) * W2 + (m & 255)] = st[n * STP + m];
        }
    }
}

// ---------------- launch ----------------
extern "C" void kernel_launch(void* const* d_in, const int* in_sizes, int n_in,
                              void* d_out, int out_size)
{
    const float* x      = (const float*)d_in[0];
    const float* w_pre  = (const float*)d_in[1];
    const float* b_pre  = (const float*)d_in[2];
    const float* w_post = (const float*)d_in[3];
    const float* b_post = (const float*)d_in[4];
    float* out = (float*)d_out;

    __half *xt, *up, *wt1, *wt2;
    cudaGetSymbolAddress((void**)&xt,  g_xt);
    cudaGetSymbolAddress((void**)&up,  g_up);
    cudaGetSymbolAddress((void**)&wt1, g_wt1);
    cudaGetSymbolAddress((void**)&wt2, g_wt2);

    // conv1: max(patch 520*144 + 2*128*144 = 111,744; staging 128*260*4 = 133,120)
    const int smem1 = 133120;
    // conv2: patch 1032*144 + 2*64*144 = 167,040 (staging 64*516*4 = 132,096 fits)
    const int smem2 = 167040;
    cudaFuncSetAttribute(gemm_conv<true>,  cudaFuncAttributeMaxDynamicSharedMemorySize, smem1);
    cudaFuncSetAttribute(gemm_conv<false>, cudaFuncAttributeMaxDynamicSharedMemorySize, smem2);

    prep_x<<<dim3(4, 128, 16), 256>>>(x, xt);
    prep_w<<<(9 * 256 * 64 + 255) / 256, 256>>>(w_pre, wt1, 256, 1);
    prep_w<<<(9 * 64 * 64 + 255) / 256, 256>>>(w_post, wt2, 64, 0);

    gemm_conv<true><<<dim3(2, 64, 16), NTHREADS, smem1>>>(xt, wt1, b_pre, nullptr, up);
    gemm_conv<false><<<dim3(1, 128, 16), NTHREADS, smem2>>>(up, wt2, b_post, out, nullptr);
}

// round 13
// speedup vs baseline: 2.7576x; 1.0635x over previous
#include <cuda_runtime.h>
#include <cuda_fp16.h>
#include <cstdint>

// ---------------- problem constants ----------------
#define BB    16
#define H1    128
#define W1    128
#define H2    256
#define W2    256

// ---------------- scratch ----------------
__device__ __align__(16) __half g_xt[(size_t)BB * H1 * W1 * 64];    // x NHWC fp16
__device__ __align__(16) __half g_up[(size_t)BB * H2 * W2 * 64];    // upsampled NHWC fp16
__device__ __align__(16) __half g_wt1[(size_t)9 * 256 * 64];        // conv1 weights [tap][n][64] (swizzled rows)
__device__ __align__(16) __half g_wt2[(size_t)9 * 64 * 64];         // conv2 weights (swizzled rows)

#define NTHREADS 512

__device__ __forceinline__ uint32_t smem_u32(const void* p) {
    uint32_t a;
    asm("{ .reg .u64 t; cvta.to.shared.u64 t, %1; cvt.u32.u64 %0, t; }" : "=r"(a) : "l"(p));
    return a;
}

#define LDSM4(r, a) \
    asm volatile("ldmatrix.sync.aligned.m8n8.x4.shared.b16 {%0,%1,%2,%3}, [%4];" \
        : "=r"((r)[0]), "=r"((r)[1]), "=r"((r)[2]), "=r"((r)[3]) : "r"(a))
#define MMAH(c, a, b) \
    asm volatile("mma.sync.aligned.m16n8k16.row.col.f32.f16.f16.f32 " \
        "{%0,%1,%2,%3},{%4,%5,%6,%7},{%8,%9},{%0,%1,%2,%3};" \
        : "+f"((c)[0]), "+f"((c)[1]), "+f"((c)[2]), "+f"((c)[3]) \
        : "r"((a)[0]), "r"((a)[1]), "r"((a)[2]), "r"((a)[3]), "r"((b)[0]), "r"((b)[1]))
#define CPASYNC(dst, src) \
    asm volatile("cp.async.cg.shared.global [%0], [%1], 16;" :: "r"(dst), "l"(src))
#define CPASYNC_Z(dst, src, sz) \
    asm volatile("cp.async.cg.shared.global [%0], [%1], 16, %2;" :: "r"(dst), "l"(src), "r"(sz))
#define CPCOMMIT() asm volatile("cp.async.commit_group;")

union HF8 { __half h[8]; uint4 v; };

// ---------------- prep: x NCHW fp32 -> NHWC fp16 ----------------
__global__ void prep_x(const float* __restrict__ x, __half* __restrict__ xt) {
    __shared__ float s[64][33];
    int lane = threadIdx.x & 31, ty = threadIdx.x >> 5;
    int w0 = blockIdx.x * 32, h = blockIdx.y, b = blockIdx.z;
    #pragma unroll
    for (int i = 0; i < 8; i++) {
        int ci = i * 8 + ty;
        s[ci][lane] = x[(((size_t)b * 64 + ci) * H1 + h) * W1 + w0 + lane];
    }
    __syncthreads();
    int wp = threadIdx.x >> 3, seg = threadIdx.x & 7;
    HF8 v;
    #pragma unroll
    for (int j = 0; j < 8; j++) v.h[j] = __float2half_rn(s[seg * 8 + j][wp]);
    size_t base = (((size_t)b * H1 + h) * W1 + (w0 + wp)) * 64;
    *(uint4*)&xt[base + seg * 8] = v.v;
}

// ---------------- prep: weights OIHW -> [tap][n][64] fp16, 16B-chunk XOR-swizzled ----------------
// conv1 n-order: n = cch*128 + (g*32 + cc)  ->  oc = g*64 + cch*32 + cc
__global__ void prep_w(const float* __restrict__ w, __half* __restrict__ wt,
                       int NT, int conv1) {
    int idx = blockIdx.x * 256 + threadIdx.x;
    if (idx >= 9 * NT * 64) return;
    int ci = idx & 63;
    int rem = idx >> 6;
    int n = rem % NT, tap = rem / NT;
    int oc;
    if (conv1) {
        int cch = n >> 7, nl = n & 127;
        oc = ((nl >> 5) << 6) + (cch << 5) + (nl & 31);
    } else oc = n;
    float v = w[((size_t)oc * 64 + ci) * 9 + tap];
    char* base = (char*)wt + ((size_t)tap * NT + n) * 128;
    int sw = (ci >> 3) ^ (n & 7);                 // swizzled 16B chunk
    *(__half*)(base + sw * 16 + (ci & 7) * 2) = __float2half_rn(v);
}

// ---------------- implicit-GEMM conv via fp16 mma.sync, resident-B, barrier-free loop ----------------
// conv1: M=256 (row pair of 128), NT=128, warps 4m x 4n.
// conv2: M=512 (row pair of 256), NT=64,  warps 8m x 2n.
// smem: patch rows 128B each (swizzled chunks), then B: 9*NT rows 128B each (swizzled chunks).
template<bool CONV1>
__global__ void __launch_bounds__(NTHREADS)
gemm_conv(const __half* __restrict__ xin,
          const __half* __restrict__ wt,
          const float* __restrict__ bias,
          float* __restrict__ out,            // conv2 only
          __half* __restrict__ up)            // conv1 only
{
    constexpr int MTILES = 4, NTILES = 4;
    constexpr int NT     = CONV1 ? 128 : 64;
    constexpr int NTOT   = CONV1 ? 256 : 64;
    constexpr int PC     = CONV1 ? 130 : 258;     // patch cols (halo)
    constexpr int PROWS  = 4 * PC;                // 520 / 1032
    constexpr int BBOFF  = PROWS * 128;
    constexpr int MROW   = CONV1 ? 128 : 256;     // out cols per row
    constexpr int STP    = CONV1 ? 260 : 516;     // staging pitch (floats)
    const int Hin = CONV1 ? H1 : H2;
    const int Win = CONV1 ? W1 : W2;

    extern __shared__ __align__(16) char smem[];
    const uint32_t sb = smem_u32(smem);
    const int tid = threadIdx.x, wid = tid >> 5, lane = tid & 31;
    const int wm  = CONV1 ? (wid >> 2) : (wid >> 1);
    const int wn  = CONV1 ? (wid & 3)  : (wid & 1);
    const int wmr = CONV1 ? (wm >> 1) : (wm >> 2);          // out row 0/1
    const int wmc = CONV1 ? ((wm & 1) * 64) : ((wm & 3) * 64);

    const int cch = CONV1 ? (int)blockIdx.x : 0;
    const int h0  = blockIdx.y * 2;
    const int b   = blockIdx.z;
    const int nbase_g = CONV1 ? cch * 128 : 0;

    // ---- one cp.async group: A patch (zero-filled halo) + ALL 9 B tap tiles ----
    {
        for (int i = tid; i < PROWS * 8; i += NTHREADS) {
            int row = i >> 3, c = i & 7;
            int hh = row / PC, ww = row - hh * PC;
            int gh = h0 - 1 + hh, gw = ww - 1;
            bool ok = (gh >= 0 && gh < Hin && gw >= 0 && gw < Win);
            const char* src = (const char*)xin
                + (ok ? (((size_t)(b * Hin + gh) * Win + gw) * 128 + c * 16) : 0);
            CPASYNC_Z(sb + row * 128 + ((c ^ (row & 7)) << 4), src, ok ? 16 : 0);
        }
        const char* wg = (const char*)wt;
        for (int i = tid; i < 9 * NT * 8; i += NTHREADS) {
            int n9 = i >> 3, c = i & 7;          // n9 = tap*NT + n  (rows already swizzled in gmem)
            int tap = n9 / NT, n = n9 - tap * NT;
            CPASYNC(sb + BBOFF + n9 * 128 + c * 16,
                    wg + ((size_t)(tap * NTOT + nbase_g + n) * 128) + c * 16);
        }
        CPCOMMIT();
    }

    float acc[MTILES][NTILES][4];
    #pragma unroll
    for (int mt = 0; mt < MTILES; mt++)
        #pragma unroll
        for (int nt = 0; nt < NTILES; nt++)
            #pragma unroll
            for (int q = 0; q < 4; q++) acc[mt][nt][q] = 0.0f;

    const uint32_t aLaneRow = (lane & 15);
    const uint32_t hiA      = (lane >> 4);        // A k-half chunk select
    const uint32_t bRow0    = ((lane >> 4) * 8) + (lane & 7);
    const uint32_t hiB      = ((lane >> 3) & 1);  // B k-half chunk select

    asm volatile("cp.async.wait_group 0;");
    __syncthreads();

    // ---- barrier-free mainloop: 9 taps x 4 ks of pure LDSM+MMA ----
    #pragma unroll 1
    for (int tap = 0; tap < 9; tap++) {
        const int dy = tap / 3, dx = tap % 3;
        const uint32_t rowA0 = (uint32_t)((wmr + dy) * PC + dx + wmc) + aLaneRow;
        const uint32_t nrow0 = (uint32_t)(wn * 32) + bRow0;
        const uint32_t aTap  = sb + rowA0 * 128;
        const uint32_t bTap  = sb + BBOFF + (tap * NT + nrow0) * 128;
        const uint32_t xa    = rowA0 & 7;
        const uint32_t xb    = nrow0 & 7;

        #pragma unroll
        for (int ks = 0; ks < 4; ks++) {
            const uint32_t aAddr = aTap + (((2 * ks + hiA) ^ xa) << 4);
            const uint32_t bAddr = bTap + (((2 * ks + hiB) ^ xb) << 4);
            uint32_t aF[MTILES][4], bF[8];
            #pragma unroll
            for (int mt = 0; mt < MTILES; mt++) LDSM4(aF[mt], aAddr + mt * 2048);
            #pragma unroll
            for (int p = 0; p < 2; p++) LDSM4(&bF[4 * p], bAddr + p * 2048);
            #pragma unroll
            for (int mt = 0; mt < MTILES; mt++)
                #pragma unroll
                for (int nt = 0; nt < NTILES; nt++) MMAH(acc[mt][nt], aF[mt], &bF[2 * nt]);
        }
    }

    // ---- stage (n, m) fp32 + bias into smem (reuse patch+B area) ----
    __syncthreads();
    float* st = (float*)smem;
    #pragma unroll
    for (int mt = 0; mt < MTILES; mt++)
        #pragma unroll
        for (int nt = 0; nt < NTILES; nt++) {
            int nl = wn * 32 + nt * 8 + (lane & 3) * 2;
            int m  = wmr * MROW + wmc + mt * 16 + (lane >> 2);
            float bv0, bv1;
            if (CONV1) {
                int oc0 = ((nl >> 5) << 6) + (cch << 5) + (nl & 31);
                bv0 = __ldg(&bias[oc0]);
                bv1 = __ldg(&bias[oc0 + 1]);
            } else {
                bv0 = __ldg(&bias[nl]);
                bv1 = __ldg(&bias[nl + 1]);
            }
            st[(nl + 0) * STP + m]     = acc[mt][nt][0] + bv0;
            st[(nl + 1) * STP + m]     = acc[mt][nt][1] + bv1;
            st[(nl + 0) * STP + m + 8] = acc[mt][nt][2] + bv0;
            st[(nl + 1) * STP + m + 8] = acc[mt][nt][3] + bv1;
        }
    __syncthreads();

    if (CONV1) {
        // wavelet mix -> fp16 upsampled NHWC. 1024 items: m(256) x oct(4)
        #pragma unroll
        for (int it = 0; it < 2; it++) {
            int item = it * NTHREADS + tid;
            int m = item >> 2, oct = item & 3;
            int mr = m >> 7, mc = m & 127;
            float vll[8], vlh[8], vhl[8], vhh[8];
            #pragma unroll
            for (int j = 0; j < 8; j++) {
                int r = oct * 8 + j;
                vll[j] = st[(r)      * STP + m];
                vlh[j] = st[(r + 32) * STP + m];
                vhl[j] = st[(r + 64) * STP + m];
                vhh[j] = st[(r + 96) * STP + m];
            }
            HF8 q[4];
            #pragma unroll
            for (int j = 0; j < 8; j++) {
                float ee = 0.5f * (vll[j] + vlh[j] + vhl[j] + vhh[j]);
                float eo = 0.5f * (vll[j] - vlh[j] + vhl[j] - vhh[j]);
                float oe = 0.5f * (vll[j] + vlh[j] - vhl[j] - vhh[j]);
                float oo = 0.5f * (vll[j] - vlh[j] - vhl[j] + vhh[j]);
                q[0].h[j] = __float2half_rn(ee);
                q[1].h[j] = __float2half_rn(eo);
                q[2].h[j] = __float2half_rn(oe);
                q[3].h[j] = __float2half_rn(oo);
            }
            int ccb = cch * 32 + oct * 8;
            #pragma unroll
            for (int p = 0; p < 4; p++) {
                int dyp = p >> 1, dxp = p & 1;
                size_t px = (((size_t)b * H2 + 2 * (h0 + mr) + dyp) * W2 + 2 * mc + dxp) * 64;
                *(uint4*)&up[px + ccb] = q[p].v;
            }
        }
    } else {
        for (int i = tid; i < 64 * 512; i += NTHREADS) {
            int n = i >> 9, m = i & 511;
            out[((size_t)(b * 64 + n) * H2 + h0 + (m >> 8)) * W2 + (m & 255)] = st[n * STP + m];
        }
    }
}

// ---------------- launch ----------------
extern "C" void kernel_launch(void* const* d_in, const int* in_sizes, int n_in,
                              void* d_out, int out_size)
{
    const float* x      = (const float*)d_in[0];
    const float* w_pre  = (const float*)d_in[1];
    const float* b_pre  = (const float*)d_in[2];
    const float* w_post = (const float*)d_in[3];
    const float* b_post = (const float*)d_in[4];
    float* out = (float*)d_out;

    __half *xt, *up, *wt1, *wt2;
    cudaGetSymbolAddress((void**)&xt,  g_xt);
    cudaGetSymbolAddress((void**)&up,  g_up);
    cudaGetSymbolAddress((void**)&wt1, g_wt1);
    cudaGetSymbolAddress((void**)&wt2, g_wt2);

    // conv1: patch 520*128 = 66,560 + B 9*128*128 = 147,456 -> 214,016  (staging 133,120 fits)
    const int smem1 = 214016;
    // conv2: patch 1032*128 = 132,096 + B 9*64*128 = 73,728 -> 205,824 (staging 132,096 fits)
    const int smem2 = 205824;
    cudaFuncSetAttribute(gemm_conv<true>,  cudaFuncAttributeMaxDynamicSharedMemorySize, smem1);
    cudaFuncSetAttribute(gemm_conv<false>, cudaFuncAttributeMaxDynamicSharedMemorySize, smem2);

    prep_x<<<dim3(4, 128, 16), 256>>>(x, xt);
    prep_w<<<(9 * 256 * 64 + 255) / 256, 256>>>(w_pre, wt1, 256, 1);
    prep_w<<<(9 * 64 * 64 + 255) / 256, 256>>>(w_post, wt2, 64, 0);

    gemm_conv<true><<<dim3(2, 64, 16), NTHREADS, smem1>>>(xt, wt1, b_pre, nullptr, up);
    gemm_conv<false><<<dim3(1, 128, 16), NTHREADS, smem2>>>(up, wt2, b_post, out, nullptr);
}

// round 14
// speedup vs baseline: 2.8757x; 1.0428x over previous
#include <cuda_runtime.h>
#include <cuda_fp16.h>
#include <cstdint>

// ---------------- problem constants ----------------
#define BB    16
#define H1    128
#define W1    128
#define H2    256
#define W2    256
#define NSM   152

// ---------------- scratch ----------------
__device__ __align__(16) __half g_xt[(size_t)BB * H1 * W1 * 64];    // x NHWC fp16
__device__ __align__(16) __half g_up[(size_t)BB * H2 * W2 * 64];    // upsampled NHWC fp16
__device__ __align__(16) __half g_wt1[(size_t)9 * 256 * 64];        // conv1 weights [tap][n][64] (swizzled rows)
__device__ __align__(16) __half g_wt2[(size_t)9 * 64 * 64];         // conv2 weights (swizzled rows)

#define NTHREADS 512

__device__ __forceinline__ uint32_t smem_u32(const void* p) {
    uint32_t a;
    asm("{ .reg .u64 t; cvta.to.shared.u64 t, %1; cvt.u32.u64 %0, t; }" : "=r"(a) : "l"(p));
    return a;
}

#define LDSM4(r, a) \
    asm volatile("ldmatrix.sync.aligned.m8n8.x4.shared.b16 {%0,%1,%2,%3}, [%4];" \
        : "=r"((r)[0]), "=r"((r)[1]), "=r"((r)[2]), "=r"((r)[3]) : "r"(a))
#define MMAH(c, a, b) \
    asm volatile("mma.sync.aligned.m16n8k16.row.col.f32.f16.f16.f32 " \
        "{%0,%1,%2,%3},{%4,%5,%6,%7},{%8,%9},{%0,%1,%2,%3};" \
        : "+f"((c)[0]), "+f"((c)[1]), "+f"((c)[2]), "+f"((c)[3]) \
        : "r"((a)[0]), "r"((a)[1]), "r"((a)[2]), "r"((a)[3]), "r"((b)[0]), "r"((b)[1]))
#define CPASYNC(dst, src) \
    asm volatile("cp.async.cg.shared.global [%0], [%1], 16;" :: "r"(dst), "l"(src))
#define CPASYNC_Z(dst, src, sz) \
    asm volatile("cp.async.cg.shared.global [%0], [%1], 16, %2;" :: "r"(dst), "l"(src), "r"(sz))
#define CPCOMMIT() asm volatile("cp.async.commit_group;")

union HF8 { __half h[8]; uint4 v; };

// ---------------- prep: x NCHW fp32 -> NHWC fp16 ----------------
__global__ void prep_x(const float* __restrict__ x, __half* __restrict__ xt) {
    __shared__ float s[64][33];
    int lane = threadIdx.x & 31, ty = threadIdx.x >> 5;
    int w0 = blockIdx.x * 32, h = blockIdx.y, b = blockIdx.z;
    #pragma unroll
    for (int i = 0; i < 8; i++) {
        int ci = i * 8 + ty;
        s[ci][lane] = x[(((size_t)b * 64 + ci) * H1 + h) * W1 + w0 + lane];
    }
    __syncthreads();
    int wp = threadIdx.x >> 3, seg = threadIdx.x & 7;
    HF8 v;
    #pragma unroll
    for (int j = 0; j < 8; j++) v.h[j] = __float2half_rn(s[seg * 8 + j][wp]);
    size_t base = (((size_t)b * H1 + h) * W1 + (w0 + wp)) * 64;
    *(uint4*)&xt[base + seg * 8] = v.v;
}

// ---------------- prep: weights OIHW -> [tap][n][64] fp16, 16B-chunk XOR-swizzled ----------------
__global__ void prep_w(const float* __restrict__ w, __half* __restrict__ wt,
                       int NT, int conv1) {
    int idx = blockIdx.x * 256 + threadIdx.x;
    if (idx >= 9 * NT * 64) return;
    int ci = idx & 63;
    int rem = idx >> 6;
    int n = rem % NT, tap = rem / NT;
    int oc;
    if (conv1) {
        int cch = n >> 7, nl = n & 127;
        oc = ((nl >> 5) << 6) + (cch << 5) + (nl & 31);
    } else oc = n;
    float v = w[((size_t)oc * 64 + ci) * 9 + tap];
    char* base = (char*)wt + ((size_t)tap * NT + n) * 128;
    int sw = (ci >> 3) ^ (n & 7);
    *(__half*)(base + sw * 16 + (ci & 7) * 2) = __float2half_rn(v);
}

// ---------------- persistent implicit-GEMM conv, resident B, fp16 mma.sync ----------------
// conv1: M=256 (row pair of 128 cols), NT=128, warps 4m x 4n; 76 CTAs per cch.
// conv2: M=512 (row pair of 256 cols), NT=64,  warps 8m x 2n; 152 CTAs.
template<bool CONV1>
__global__ void __launch_bounds__(NTHREADS)
gemm_conv(const __half* __restrict__ xin,
          const __half* __restrict__ wt,
          const float* __restrict__ bias,
          float* __restrict__ out,            // conv2 only
          __half* __restrict__ up)            // conv1 only
{
    constexpr int MTILES = 4, NTILES = 4;
    constexpr int NT     = CONV1 ? 128 : 64;
    constexpr int NTOT   = CONV1 ? 256 : 64;
    constexpr int PC     = CONV1 ? 130 : 258;
    constexpr int PROWS  = 4 * PC;
    constexpr int BBOFF  = PROWS * 128;
    constexpr int MROW   = CONV1 ? 128 : 256;
    constexpr int STP    = CONV1 ? 130 : 516;     // staging pitch (floats) — fits in patch area
    constexpr int NTILES_TOT = CONV1 ? 1024 : 2048;
    const int Hin = CONV1 ? H1 : H2;
    const int Win = CONV1 ? W1 : W2;

    extern __shared__ __align__(16) char smem[];
    const uint32_t sb = smem_u32(smem);
    const int tid = threadIdx.x, wid = tid >> 5, lane = tid & 31;
    const int wm  = CONV1 ? (wid >> 2) : (wid >> 1);
    const int wn  = CONV1 ? (wid & 3)  : (wid & 1);
    const int wmr = CONV1 ? (wm >> 1) : (wm >> 2);
    const int wmc = CONV1 ? ((wm & 1) * 64) : ((wm & 3) * 64);

    const int cta  = blockIdx.x;
    const int cch  = CONV1 ? (cta & 1) : 0;
    const int slot = CONV1 ? (cta >> 1) : cta;
    const int tstride = CONV1 ? (NSM / 2) : NSM;
    const int nbase_g = CONV1 ? cch * 128 : 0;

    const uint32_t aLaneRow = (lane & 15);
    const uint32_t hiA      = (lane >> 4);
    const uint32_t bRow0    = ((lane >> 4) * 8) + (lane & 7);
    const uint32_t hiB      = ((lane >> 3) & 1);

    // ---- load ALL 9 B tap tiles once (resident for the whole kernel) ----
    {
        const char* wg = (const char*)wt;
        for (int i = tid; i < 9 * NT * 8; i += NTHREADS) {
            int n9 = i >> 3, c = i & 7;
            int tap = n9 / NT, n = n9 - tap * NT;
            CPASYNC(sb + BBOFF + n9 * 128 + c * 16,
                    wg + ((size_t)(tap * NTOT + nbase_g + n) * 128) + c * 16);
        }
        CPCOMMIT();
    }

    for (int t = slot; t < NTILES_TOT; t += tstride) {
        const int h0 = CONV1 ? ((t & 63) * 2) : ((t & 127) * 2);
        const int b  = CONV1 ? (t >> 6) : (t >> 7);

        // ---- patch load (zero-filled halo) ----
        for (int i = tid; i < PROWS * 8; i += NTHREADS) {
            int row = i >> 3, c = i & 7;
            int hh = row / PC, ww = row - hh * PC;
            int gh = h0 - 1 + hh, gw = ww - 1;
            bool ok = (gh >= 0 && gh < Hin && gw >= 0 && gw < Win);
            const char* src = (const char*)xin
                + (ok ? (((size_t)(b * Hin + gh) * Win + gw) * 128 + c * 16) : 0);
            CPASYNC_Z(sb + row * 128 + ((c ^ (row & 7)) << 4), src, ok ? 16 : 0);
        }
        CPCOMMIT();
        asm volatile("cp.async.wait_group 0;");
        __syncthreads();

        float acc[MTILES][NTILES][4];
        #pragma unroll
        for (int mt = 0; mt < MTILES; mt++)
            #pragma unroll
            for (int nt = 0; nt < NTILES; nt++)
                #pragma unroll
                for (int q = 0; q < 4; q++) acc[mt][nt][q] = 0.0f;

        // ---- barrier-free mainloop ----
        #pragma unroll 1
        for (int tap = 0; tap < 9; tap++) {
            const int dy = tap / 3, dx = tap % 3;
            const uint32_t rowA0 = (uint32_t)((wmr + dy) * PC + dx + wmc) + aLaneRow;
            const uint32_t nrow0 = (uint32_t)(wn * 32) + bRow0;
            const uint32_t aTap  = sb + rowA0 * 128;
            const uint32_t bTap  = sb + BBOFF + (tap * NT + nrow0) * 128;
            const uint32_t xa    = rowA0 & 7;
            const uint32_t xb    = nrow0 & 7;
            #pragma unroll
            for (int ks = 0; ks < 4; ks++) {
                const uint32_t aAddr = aTap + (((2 * ks + hiA) ^ xa) << 4);
                const uint32_t bAddr = bTap + (((2 * ks + hiB) ^ xb) << 4);
                uint32_t aF[MTILES][4], bF[8];
                #pragma unroll
                for (int mt = 0; mt < MTILES; mt++) LDSM4(aF[mt], aAddr + mt * 2048);
                #pragma unroll
                for (int p = 0; p < 2; p++) LDSM4(&bF[4 * p], bAddr + p * 2048);
                #pragma unroll
                for (int mt = 0; mt < MTILES; mt++)
                    #pragma unroll
                    for (int nt = 0; nt < NTILES; nt++) MMAH(acc[mt][nt], aF[mt], &bF[2 * nt]);
            }
        }
        __syncthreads();

        float* st = (float*)smem;
        if (CONV1) {
            // epilogue in two m-halves (staging fits inside patch area, B stays live)
            #pragma unroll
            for (int half = 0; half < 2; half++) {
                if (wmr == half) {
                    #pragma unroll
                    for (int mt = 0; mt < MTILES; mt++)
                        #pragma unroll
                        for (int nt = 0; nt < NTILES; nt++) {
                            int nl = wn * 32 + nt * 8 + (lane & 3) * 2;
                            int m  = wmc + mt * 16 + (lane >> 2);
                            int oc0 = ((nl >> 5) << 6) + (cch << 5) + (nl & 31);
                            float bv0 = __ldg(&bias[oc0]);
                            float bv1 = __ldg(&bias[oc0 + 1]);
                            st[(nl + 0) * STP + m]     = acc[mt][nt][0] + bv0;
                            st[(nl + 1) * STP + m]     = acc[mt][nt][1] + bv1;
                            st[(nl + 0) * STP + m + 8] = acc[mt][nt][2] + bv0;
                            st[(nl + 1) * STP + m + 8] = acc[mt][nt][3] + bv1;
                        }
                }
                __syncthreads();
                {   // 512 items: m(128) x oct(4)
                    int m = tid >> 2, oct = tid & 3;
                    float vll[8], vlh[8], vhl[8], vhh[8];
                    #pragma unroll
                    for (int j = 0; j < 8; j++) {
                        int r = oct * 8 + j;
                        vll[j] = st[(r)      * STP + m];
                        vlh[j] = st[(r + 32) * STP + m];
                        vhl[j] = st[(r + 64) * STP + m];
                        vhh[j] = st[(r + 96) * STP + m];
                    }
                    HF8 q[4];
                    #pragma unroll
                    for (int j = 0; j < 8; j++) {
                        float ee = 0.5f * (vll[j] + vlh[j] + vhl[j] + vhh[j]);
                        float eo = 0.5f * (vll[j] - vlh[j] + vhl[j] - vhh[j]);
                        float oe = 0.5f * (vll[j] + vlh[j] - vhl[j] - vhh[j]);
                        float oo = 0.5f * (vll[j] - vlh[j] - vhl[j] + vhh[j]);
                        q[0].h[j] = __float2half_rn(ee);
                        q[1].h[j] = __float2half_rn(eo);
                        q[2].h[j] = __float2half_rn(oe);
                        q[3].h[j] = __float2half_rn(oo);
                    }
                    int ccb = cch * 32 + oct * 8;
                    #pragma unroll
                    for (int p = 0; p < 4; p++) {
                        int dyp = p >> 1, dxp = p & 1;
                        size_t px = (((size_t)b * H2 + 2 * (h0 + half) + dyp) * W2 + 2 * m + dxp) * 64;
                        *(uint4*)&up[px + ccb] = q[p].v;
                    }
                }
                __syncthreads();
            }
        } else {
            #pragma unroll
            for (int mt = 0; mt < MTILES; mt++)
                #pragma unroll
                for (int nt = 0; nt < NTILES; nt++) {
                    int nl = wn * 32 + nt * 8 + (lane & 3) * 2;
                    int m  = wmr * MROW + wmc + mt * 16 + (lane >> 2);
                    float bv0 = __ldg(&bias[nl]);
                    float bv1 = __ldg(&bias[nl + 1]);
                    st[(nl + 0) * STP + m]     = acc[mt][nt][0] + bv0;
                    st[(nl + 1) * STP + m]     = acc[mt][nt][1] + bv1;
                    st[(nl + 0) * STP + m + 8] = acc[mt][nt][2] + bv0;
                    st[(nl + 1) * STP + m + 8] = acc[mt][nt][3] + bv1;
                }
            __syncthreads();
            for (int i = tid; i < 64 * 512; i += NTHREADS) {
                int n = i >> 9, m = i & 511;
                out[((size_t)(b * 64 + n) * H2 + h0 + (m >> 8)) * W2 + (m & 255)] = st[n * STP + m];
            }
            __syncthreads();
        }
    }
}

// ---------------- launch ----------------
extern "C" void kernel_launch(void* const* d_in, const int* in_sizes, int n_in,
                              void* d_out, int out_size)
{
    const float* x      = (const float*)d_in[0];
    const float* w_pre  = (const float*)d_in[1];
    const float* b_pre  = (const float*)d_in[2];
    const float* w_post = (const float*)d_in[3];
    const float* b_post = (const float*)d_in[4];
    float* out = (float*)d_out;

    __half *xt, *up, *wt1, *wt2;
    cudaGetSymbolAddress((void**)&xt,  g_xt);
    cudaGetSymbolAddress((void**)&up,  g_up);
    cudaGetSymbolAddress((void**)&wt1, g_wt1);
    cudaGetSymbolAddress((void**)&wt2, g_wt2);

    // conv1: patch 520*128 = 66,560 + B 9*128*128 = 147,456 -> 214,016
    const int smem1 = 214016;
    // conv2: patch 1032*128 = 132,096 + B 9*64*128 = 73,728 -> 205,824
    const int smem2 = 205824;
    cudaFuncSetAttribute(gemm_conv<true>,  cudaFuncAttributeMaxDynamicSharedMemorySize, smem1);
    cudaFuncSetAttribute(gemm_conv<false>, cudaFuncAttributeMaxDynamicSharedMemorySize, smem2);

    prep_x<<<dim3(4, 128, 16), 256>>>(x, xt);
    prep_w<<<(9 * 256 * 64 + 255) / 256, 256>>>(w_pre, wt1, 256, 1);
    prep_w<<<(9 * 64 * 64 + 255) / 256, 256>>>(w_post, wt2, 64, 0);

    gemm_conv<true><<<NSM, NTHREADS, smem1>>>(xt, wt1, b_pre, nullptr, up);
    gemm_conv<false><<<NSM, NTHREADS, smem2>>>(up, wt2, b_post, out, nullptr);
}

// round 15
// speedup vs baseline: 2.9683x; 1.0322x over previous
#include <cuda_runtime.h>
#include <cuda_fp16.h>
#include <cstdint>

// ---------------- problem constants ----------------
#define BB    16
#define H1    128
#define W1    128
#define H2    256
#define W2    256
#define NSM   152

// ---------------- scratch ----------------
__device__ __align__(16) __half g_xt[(size_t)BB * H1 * W1 * 64];    // x NHWC fp16
__device__ __align__(16) __half g_up[(size_t)BB * H2 * W2 * 64];    // upsampled NHWC fp16
__device__ __align__(16) __half g_wt1[(size_t)9 * 256 * 64];        // conv1 weights [tap][n][64] (swizzled rows)
__device__ __align__(16) __half g_wt2[(size_t)9 * 64 * 64];         // conv2 weights (swizzled rows)

#define NTHREADS 512
#define PC       130
#define PROWS    520
#define PB       66560              // one patch buffer (bytes)
#define BOFF     (2 * PB)           // B tiles offset (133,120)
#define STP      260                // staging pitch (floats); 64*260*4 = 66,560 = PB

__device__ __forceinline__ uint32_t smem_u32(const void* p) {
    uint32_t a;
    asm("{ .reg .u64 t; cvta.to.shared.u64 t, %1; cvt.u32.u64 %0, t; }" : "=r"(a) : "l"(p));
    return a;
}

#define LDSM4(r, a) \
    asm volatile("ldmatrix.sync.aligned.m8n8.x4.shared.b16 {%0,%1,%2,%3}, [%4];" \
        : "=r"((r)[0]), "=r"((r)[1]), "=r"((r)[2]), "=r"((r)[3]) : "r"(a))
#define MMAH(c, a, b) \
    asm volatile("mma.sync.aligned.m16n8k16.row.col.f32.f16.f16.f32 " \
        "{%0,%1,%2,%3},{%4,%5,%6,%7},{%8,%9},{%0,%1,%2,%3};" \
        : "+f"((c)[0]), "+f"((c)[1]), "+f"((c)[2]), "+f"((c)[3]) \
        : "r"((a)[0]), "r"((a)[1]), "r"((a)[2]), "r"((a)[3]), "r"((b)[0]), "r"((b)[1]))
#define CPASYNC(dst, src) \
    asm volatile("cp.async.cg.shared.global [%0], [%1], 16;" :: "r"(dst), "l"(src))
#define CPASYNC_Z(dst, src, sz) \
    asm volatile("cp.async.cg.shared.global [%0], [%1], 16, %2;" :: "r"(dst), "l"(src), "r"(sz))
#define CPCOMMIT() asm volatile("cp.async.commit_group;")

union HF8 { __half h[8]; uint4 v; };

// ---------------- prep: x NCHW fp32 -> NHWC fp16 ----------------
__global__ void prep_x(const float* __restrict__ x, __half* __restrict__ xt) {
    __shared__ float s[64][33];
    int lane = threadIdx.x & 31, ty = threadIdx.x >> 5;
    int w0 = blockIdx.x * 32, h = blockIdx.y, b = blockIdx.z;
    #pragma unroll
    for (int i = 0; i < 8; i++) {
        int ci = i * 8 + ty;
        s[ci][lane] = x[(((size_t)b * 64 + ci) * H1 + h) * W1 + w0 + lane];
    }
    __syncthreads();
    int wp = threadIdx.x >> 3, seg = threadIdx.x & 7;
    HF8 v;
    #pragma unroll
    for (int j = 0; j < 8; j++) v.h[j] = __float2half_rn(s[seg * 8 + j][wp]);
    size_t base = (((size_t)b * H1 + h) * W1 + (w0 + wp)) * 64;
    *(uint4*)&xt[base + seg * 8] = v.v;
}

// ---------------- prep: weights OIHW -> [tap][n][64] fp16, 16B-chunk XOR-swizzled ----------------
// conv1 n-order: n = cch*64 + g*16 + cc  ->  oc = g*64 + cch*16 + cc
__global__ void prep_w(const float* __restrict__ w, __half* __restrict__ wt,
                       int NTOT, int conv1) {
    int idx = blockIdx.x * 256 + threadIdx.x;
    if (idx >= 9 * NTOT * 64) return;
    int ci = idx & 63;
    int rem = idx >> 6;
    int n = rem % NTOT, tap = rem / NTOT;
    int oc;
    if (conv1) {
        int cch = n >> 6, g = (n >> 4) & 3, cc = n & 15;
        oc = g * 64 + cch * 16 + cc;
    } else oc = n;
    float v = w[((size_t)oc * 64 + ci) * 9 + tap];
    char* base = (char*)wt + ((size_t)tap * NTOT + n) * 128;
    int sw = (ci >> 3) ^ (n & 7);
    *(__half*)(base + sw * 16 + (ci & 7) * 2) = __float2half_rn(v);
}

// ---------------- persistent, patch-double-buffered implicit GEMM, fp16 mma.sync ----------------
// Both convs: M=256 (row pair x 128 cols), NT=64, warps 8m x 2n (MTILES=2, NTILES=4).
// conv1: 4 cch chunks x 64 rowpairs x 16 b = 1024 tiles per cch-set, 38 CTAs each.
// conv2: 2 w-halves x 128 rowpairs x 16 b = 4096 tiles, 152 CTAs.
template<bool CONV1>
__global__ void __launch_bounds__(NTHREADS)
gemm_conv(const __half* __restrict__ xin,
          const __half* __restrict__ wt,
          const float* __restrict__ bias,
          float* __restrict__ out,            // conv2 only
          __half* __restrict__ up)            // conv1 only
{
    constexpr int MTILES = 2, NTILES = 4, NT = 64;
    constexpr int NTOT   = CONV1 ? 256 : 64;
    const int Hin = CONV1 ? H1 : H2;
    const int Win = CONV1 ? W1 : W2;

    extern __shared__ __align__(16) char smem[];
    const uint32_t sb = smem_u32(smem);
    const int tid = threadIdx.x, wid = tid >> 5, lane = tid & 31;
    const int wm = wid >> 1, wn = wid & 1;       // 8 x 2 warp grid
    const int wmr = wm >> 2;                     // output local row 0/1
    const int wmc = (wm & 3) * 32;               // col base within row

    const int cta = blockIdx.x;
    const int cchx   = CONV1 ? (cta & 3) : 0;
    const int slot   = CONV1 ? (cta >> 2) : cta;
    const int stride = CONV1 ? (NSM / 4) : NSM;
    const int TOT    = CONV1 ? 1024 : 4096;
    const int nbase_g = cchx * 64;

    const uint32_t aLaneRow = (lane & 15);
    const uint32_t hiA      = (lane >> 4);
    const uint32_t bRow0    = ((lane >> 4) * 8) + (lane & 7);
    const uint32_t hiB      = ((lane >> 3) & 1);

    // ---- prologue: resident B (all 9 taps) + first patch, one group ----
    {
        const char* wg = (const char*)wt;
        for (int i = tid; i < 9 * NT * 8; i += NTHREADS) {
            int n9 = i >> 3, c = i & 7;
            int tap = n9 >> 6, n = n9 & 63;
            CPASYNC(sb + BOFF + n9 * 128 + c * 16,
                    wg + ((size_t)(tap * NTOT + nbase_g + n) * 128) + c * 16);
        }
    }
    // first patch
    if (slot < TOT) {
        const int t = slot;
        const int h0 = CONV1 ? ((t & 63) * 2) : (((t >> 1) & 127) * 2);
        const int b  = CONV1 ? (t >> 6) : (t >> 8);
        const int w0 = CONV1 ? 0 : ((t & 1) * 128);
        for (int i = tid; i < PROWS * 8; i += NTHREADS) {
            int row = i >> 3, c = i & 7;
            int hh = row / PC, ww = row - hh * PC;
            int gh = h0 - 1 + hh, gw = w0 - 1 + ww;
            bool ok = (gh >= 0 && gh < Hin && gw >= 0 && gw < Win);
            const char* src = (const char*)xin
                + (ok ? (((size_t)(b * Hin + gh) * Win + gw) * 128 + c * 16) : 0);
            CPASYNC_Z(sb + row * 128 + ((c ^ (row & 7)) << 4), src, ok ? 16 : 0);
        }
    }
    CPCOMMIT();

    int ibuf = 0;
    for (int t = slot; t < TOT; t += stride, ibuf ^= 1) {
        const int h0 = CONV1 ? ((t & 63) * 2) : (((t >> 1) & 127) * 2);
        const int b  = CONV1 ? (t >> 6) : (t >> 8);
        const int w0 = CONV1 ? 0 : ((t & 1) * 128);
        const uint32_t cur = sb + ibuf * PB;

        asm volatile("cp.async.wait_group 0;");
        __syncthreads();

        // ---- prefetch NEXT tile's patch into the other buffer ----
        {
            const int t2 = t + stride;
            if (t2 < TOT) {
                const int h2 = CONV1 ? ((t2 & 63) * 2) : (((t2 >> 1) & 127) * 2);
                const int b2 = CONV1 ? (t2 >> 6) : (t2 >> 8);
                const int w2 = CONV1 ? 0 : ((t2 & 1) * 128);
                const uint32_t nxt = sb + (ibuf ^ 1) * PB;
                for (int i = tid; i < PROWS * 8; i += NTHREADS) {
                    int row = i >> 3, c = i & 7;
                    int hh = row / PC, ww = row - hh * PC;
                    int gh = h2 - 1 + hh, gw = w2 - 1 + ww;
                    bool ok = (gh >= 0 && gh < Hin && gw >= 0 && gw < Win);
                    const char* src = (const char*)xin
                        + (ok ? (((size_t)(b2 * Hin + gh) * Win + gw) * 128 + c * 16) : 0);
                    CPASYNC_Z(nxt + row * 128 + ((c ^ (row & 7)) << 4), src, ok ? 16 : 0);
                }
                CPCOMMIT();
            }
        }

        float acc[MTILES][NTILES][4];
        #pragma unroll
        for (int mt = 0; mt < MTILES; mt++)
            #pragma unroll
            for (int nt = 0; nt < NTILES; nt++)
                #pragma unroll
                for (int q = 0; q < 4; q++) acc[mt][nt][q] = 0.0f;

        // ---- barrier-free mainloop ----
        #pragma unroll 1
        for (int tap = 0; tap < 9; tap++) {
            const int dy = tap / 3, dx = tap % 3;
            const uint32_t rowA0 = (uint32_t)((wmr + dy) * PC + dx + wmc) + aLaneRow;
            const uint32_t nrow0 = (uint32_t)(wn * 32) + bRow0;
            const uint32_t aTap  = cur + rowA0 * 128;
            const uint32_t bTap  = sb + BOFF + (tap * NT + nrow0) * 128;
            const uint32_t xa    = rowA0 & 7;
            const uint32_t xb    = nrow0 & 7;
            #pragma unroll
            for (int ks = 0; ks < 4; ks++) {
                const uint32_t aAddr = aTap + (((2 * ks + hiA) ^ xa) << 4);
                const uint32_t bAddr = bTap + (((2 * ks + hiB) ^ xb) << 4);
                uint32_t aF[MTILES][4], bF[8];
                #pragma unroll
                for (int mt = 0; mt < MTILES; mt++) LDSM4(aF[mt], aAddr + mt * 2048);
                #pragma unroll
                for (int p = 0; p < 2; p++) LDSM4(&bF[4 * p], bAddr + p * 2048);
                #pragma unroll
                for (int mt = 0; mt < MTILES; mt++)
                    #pragma unroll
                    for (int nt = 0; nt < NTILES; nt++) MMAH(acc[mt][nt], aF[mt], &bF[2 * nt]);
            }
        }
        __syncthreads();

        // ---- stage (n, m) fp32 + bias into the CONSUMED patch buffer ----
        float* st = (float*)(smem + ibuf * PB);
        #pragma unroll
        for (int mt = 0; mt < MTILES; mt++)
            #pragma unroll
            for (int nt = 0; nt < NTILES; nt++) {
                int nl = wn * 32 + nt * 8 + (lane & 3) * 2;
                int m  = wm * 32 + mt * 16 + (lane >> 2);
                float bv0, bv1;
                if (CONV1) {
                    int g = nl >> 4, cc = nl & 15;
                    int oc0 = g * 64 + cchx * 16 + cc;
                    bv0 = __ldg(&bias[oc0]);
                    bv1 = __ldg(&bias[oc0 + 1]);
                } else {
                    bv0 = __ldg(&bias[nl]);
                    bv1 = __ldg(&bias[nl + 1]);
                }
                st[(nl + 0) * STP + m]     = acc[mt][nt][0] + bv0;
                st[(nl + 1) * STP + m]     = acc[mt][nt][1] + bv1;
                st[(nl + 0) * STP + m + 8] = acc[mt][nt][2] + bv0;
                st[(nl + 1) * STP + m + 8] = acc[mt][nt][3] + bv1;
            }
        __syncthreads();

        if (CONV1) {
            // wavelet mix -> fp16 up NHWC. 512 items: m(256) x oct(2) ; channels cc = oct*8+j
            int m = tid >> 1, oct = tid & 1;
            int mr = m >> 7, mc = m & 127;
            float vll[8], vlh[8], vhl[8], vhh[8];
            #pragma unroll
            for (int j = 0; j < 8; j++) {
                int cc = oct * 8 + j;
                vll[j] = st[(0 * 16 + cc) * STP + m];
                vlh[j] = st[(1 * 16 + cc) * STP + m];
                vhl[j] = st[(2 * 16 + cc) * STP + m];
                vhh[j] = st[(3 * 16 + cc) * STP + m];
            }
            HF8 q[4];
            #pragma unroll
            for (int j = 0; j < 8; j++) {
                float ee = 0.5f * (vll[j] + vlh[j] + vhl[j] + vhh[j]);
                float eo = 0.5f * (vll[j] - vlh[j] + vhl[j] - vhh[j]);
                float oe = 0.5f * (vll[j] + vlh[j] - vhl[j] - vhh[j]);
                float oo = 0.5f * (vll[j] - vlh[j] - vhl[j] + vhh[j]);
                q[0].h[j] = __float2half_rn(ee);
                q[1].h[j] = __float2half_rn(eo);
                q[2].h[j] = __float2half_rn(oe);
                q[3].h[j] = __float2half_rn(oo);
            }
            int ccb = cchx * 16 + oct * 8;
            #pragma unroll
            for (int p = 0; p < 4; p++) {
                int dyp = p >> 1, dxp = p & 1;
                size_t px = (((size_t)b * H2 + 2 * (h0 + mr) + dyp) * W2 + 2 * mc + dxp) * 64;
                *(uint4*)&up[px + ccb] = q[p].v;
            }
        } else {
            for (int i = tid; i < 64 * 256; i += NTHREADS) {
                int n = i >> 8, m = i & 255;
                out[((size_t)(b * 64 + n) * H2 + h0 + (m >> 7)) * W2 + w0 + (m & 127)]
                    = st[n * STP + m];
            }
        }
    }
}

// ---------------- launch ----------------
extern "C" void kernel_launch(void* const* d_in, const int* in_sizes, int n_in,
                              void* d_out, int out_size)
{
    const float* x      = (const float*)d_in[0];
    const float* w_pre  = (const float*)d_in[1];
    const float* b_pre  = (const float*)d_in[2];
    const float* w_post = (const float*)d_in[3];
    const float* b_post = (const float*)d_in[4];
    float* out = (float*)d_out;

    __half *xt, *up, *wt1, *wt2;
    cudaGetSymbolAddress((void**)&xt,  g_xt);
    cudaGetSymbolAddress((void**)&up,  g_up);
    cudaGetSymbolAddress((void**)&wt1, g_wt1);
    cudaGetSymbolAddress((void**)&wt2, g_wt2);

    // both: 2 patches (133,120) + B 9*64*128 (73,728) = 206,848
    const int smemB = 206848;
    cudaFuncSetAttribute(gemm_conv<true>,  cudaFuncAttributeMaxDynamicSharedMemorySize, smemB);
    cudaFuncSetAttribute(gemm_conv<false>, cudaFuncAttributeMaxDynamicSharedMemorySize, smemB);

    prep_x<<<dim3(4, 128, 16), 256>>>(x, xt);
    prep_w<<<(9 * 256 * 64 + 255) / 256, 256>>>(w_pre, wt1, 256, 1);
    prep_w<<<(9 * 64 * 64 + 255) / 256, 256>>>(w_post, wt2, 64, 0);

    gemm_conv<true><<<NSM, NTHREADS, smemB>>>(xt, wt1, b_pre, nullptr, up);
    gemm_conv<false><<<NSM, NTHREADS, smemB>>>(up, wt2, b_post, out, nullptr);
}

// round 16
// speedup vs baseline: 3.1714x; 1.0684x over previous
#include <cuda_runtime.h>
#include <cuda_fp16.h>
#include <cstdint>

// ---------------- problem constants ----------------
#define BB    16
#define H1    128
#define W1    128
#define H2    256
#define W2    256
#define NSM   152

// ---------------- scratch ----------------
__device__ __align__(16) __half g_xt[(size_t)BB * H1 * W1 * 64];    // x NHWC fp16
__device__ __align__(16) __half g_up[(size_t)BB * H2 * W2 * 64];    // upsampled NHWC fp16
__device__ __align__(16) __half g_wt1[(size_t)9 * 256 * 64];        // conv1 weights [tap][n][64] (swizzled rows)
__device__ __align__(16) __half g_wt2[(size_t)9 * 64 * 64];         // conv2 weights (swizzled rows)

#define NTHREADS 512
#define PC       130
#define PROWS    520
#define PB       66560              // one patch buffer (bytes)
#define BOFF     (2 * PB)           // B tiles offset (133,120)
#define STP      260                // staging pitch (floats); 64*260*4 = 66,560 = PB

__device__ __forceinline__ uint32_t smem_u32(const void* p) {
    uint32_t a;
    asm("{ .reg .u64 t; cvta.to.shared.u64 t, %1; cvt.u32.u64 %0, t; }" : "=r"(a) : "l"(p));
    return a;
}

#define LDSM4(r, a) \
    asm volatile("ldmatrix.sync.aligned.m8n8.x4.shared.b16 {%0,%1,%2,%3}, [%4];" \
        : "=r"((r)[0]), "=r"((r)[1]), "=r"((r)[2]), "=r"((r)[3]) : "r"(a))
#define MMAH(c, a, b) \
    asm volatile("mma.sync.aligned.m16n8k16.row.col.f32.f16.f16.f32 " \
        "{%0,%1,%2,%3},{%4,%5,%6,%7},{%8,%9},{%0,%1,%2,%3};" \
        : "+f"((c)[0]), "+f"((c)[1]), "+f"((c)[2]), "+f"((c)[3]) \
        : "r"((a)[0]), "r"((a)[1]), "r"((a)[2]), "r"((a)[3]), "r"((b)[0]), "r"((b)[1]))
#define CPASYNC(dst, src) \
    asm volatile("cp.async.cg.shared.global [%0], [%1], 16;" :: "r"(dst), "l"(src))
#define CPASYNC_Z(dst, src, sz) \
    asm volatile("cp.async.cg.shared.global [%0], [%1], 16, %2;" :: "r"(dst), "l"(src), "r"(sz))
#define CPCOMMIT() asm volatile("cp.async.commit_group;")

union HF8 { __half h[8]; uint4 v; };

// ---------------- prep: x NCHW fp32 -> NHWC fp16 ----------------
__global__ void prep_x(const float* __restrict__ x, __half* __restrict__ xt) {
    __shared__ float s[64][33];
    int lane = threadIdx.x & 31, ty = threadIdx.x >> 5;
    int w0 = blockIdx.x * 32, h = blockIdx.y, b = blockIdx.z;
    #pragma unroll
    for (int i = 0; i < 8; i++) {
        int ci = i * 8 + ty;
        s[ci][lane] = x[(((size_t)b * 64 + ci) * H1 + h) * W1 + w0 + lane];
    }
    __syncthreads();
    int wp = threadIdx.x >> 3, seg = threadIdx.x & 7;
    HF8 v;
    #pragma unroll
    for (int j = 0; j < 8; j++) v.h[j] = __float2half_rn(s[seg * 8 + j][wp]);
    size_t base = (((size_t)b * H1 + h) * W1 + (w0 + wp)) * 64;
    *(uint4*)&xt[base + seg * 8] = v.v;
}

// ---------------- prep: weights OIHW -> [tap][n][64] fp16, 16B-chunk XOR-swizzled ----------------
// conv1 n-order: n = cch*64 + g*16 + cc  ->  oc = g*64 + cch*16 + cc
__global__ void prep_w(const float* __restrict__ w, __half* __restrict__ wt,
                       int NTOT, int conv1) {
    int idx = blockIdx.x * 256 + threadIdx.x;
    if (idx >= 9 * NTOT * 64) return;
    int ci = idx & 63;
    int rem = idx >> 6;
    int n = rem % NTOT, tap = rem / NTOT;
    int oc;
    if (conv1) {
        int cch = n >> 6, g = (n >> 4) & 3, cc = n & 15;
        oc = g * 64 + cch * 16 + cc;
    } else oc = n;
    float v = w[((size_t)oc * 64 + ci) * 9 + tap];
    char* base = (char*)wt + ((size_t)tap * NTOT + n) * 128;
    int sw = (ci >> 3) ^ (n & 7);
    *(__half*)(base + sw * 16 + (ci & 7) * 2) = __float2half_rn(v);
}

// ---------------- persistent, patch-double-buffered implicit GEMM, fp16 mma.sync ----------------
// Both convs: M=256 (row pair x 128 cols), NT=64, warps 8m x 2n (MTILES=2, NTILES=4).
template<bool CONV1>
__global__ void __launch_bounds__(NTHREADS)
gemm_conv(const __half* __restrict__ xin,
          const __half* __restrict__ wt,
          const float* __restrict__ bias,
          float* __restrict__ out,            // conv2 only
          __half* __restrict__ up)            // conv1 only
{
    constexpr int MTILES = 2, NTILES = 4, NT = 64;
    constexpr int NTOT   = CONV1 ? 256 : 64;
    const int Hin = CONV1 ? H1 : H2;
    const int Win = CONV1 ? W1 : W2;

    extern __shared__ __align__(16) char smem[];
    const uint32_t sb = smem_u32(smem);
    const int tid = threadIdx.x, wid = tid >> 5, lane = tid & 31;
    const int wm = wid >> 1, wn = wid & 1;       // 8 x 2 warp grid
    const int wmr = wm >> 2;                     // output local row 0/1
    const int wmc = (wm & 3) * 32;               // col base within row

    const int cta = blockIdx.x;
    const int cchx   = CONV1 ? (cta & 3) : 0;
    const int slot   = CONV1 ? (cta >> 2) : cta;
    const int stride = CONV1 ? (NSM / 4) : NSM;
    const int TOT    = CONV1 ? 1024 : 4096;
    const int nbase_g = cchx * 64;

    const uint32_t aLaneRow = (lane & 15);
    const uint32_t hiA      = (lane >> 4);
    const uint32_t bRow0    = ((lane >> 4) * 8) + (lane & 7);
    const uint32_t hiB      = ((lane >> 3) & 1);

    // ---- prologue: resident B (all 9 taps) + first patch, one group ----
    {
        const char* wg = (const char*)wt;
        for (int i = tid; i < 9 * NT * 8; i += NTHREADS) {
            int n9 = i >> 3, c = i & 7;
            int tap = n9 >> 6, n = n9 & 63;
            CPASYNC(sb + BOFF + n9 * 128 + c * 16,
                    wg + ((size_t)(tap * NTOT + nbase_g + n) * 128) + c * 16);
        }
    }
    if (slot < TOT) {
        const int t = slot;
        const int h0 = CONV1 ? ((t & 63) * 2) : (((t >> 1) & 127) * 2);
        const int b  = CONV1 ? (t >> 6) : (t >> 8);
        const int w0 = CONV1 ? 0 : ((t & 1) * 128);
        for (int i = tid; i < PROWS * 8; i += NTHREADS) {
            int row = i >> 3, c = i & 7;
            int hh = row / PC, ww = row - hh * PC;
            int gh = h0 - 1 + hh, gw = w0 - 1 + ww;
            bool ok = (gh >= 0 && gh < Hin && gw >= 0 && gw < Win);
            const char* src = (const char*)xin
                + (ok ? (((size_t)(b * Hin + gh) * Win + gw) * 128 + c * 16) : 0);
            CPASYNC_Z(sb + row * 128 + ((c ^ (row & 7)) << 4), src, ok ? 16 : 0);
        }
    }
    CPCOMMIT();

    int ibuf = 0;
    for (int t = slot; t < TOT; t += stride, ibuf ^= 1) {
        const int h0 = CONV1 ? ((t & 63) * 2) : (((t >> 1) & 127) * 2);
        const int b  = CONV1 ? (t >> 6) : (t >> 8);
        const int w0 = CONV1 ? 0 : ((t & 1) * 128);
        const uint32_t cur = sb + ibuf * PB;

        asm volatile("cp.async.wait_group 0;");
        __syncthreads();

        // ---- prefetch NEXT tile's patch into the other buffer ----
        {
            const int t2 = t + stride;
            if (t2 < TOT) {
                const int h2 = CONV1 ? ((t2 & 63) * 2) : (((t2 >> 1) & 127) * 2);
                const int b2 = CONV1 ? (t2 >> 6) : (t2 >> 8);
                const int w2 = CONV1 ? 0 : ((t2 & 1) * 128);
                const uint32_t nxt = sb + (ibuf ^ 1) * PB;
                for (int i = tid; i < PROWS * 8; i += NTHREADS) {
                    int row = i >> 3, c = i & 7;
                    int hh = row / PC, ww = row - hh * PC;
                    int gh = h2 - 1 + hh, gw = w2 - 1 + ww;
                    bool ok = (gh >= 0 && gh < Hin && gw >= 0 && gw < Win);
                    const char* src = (const char*)xin
                        + (ok ? (((size_t)(b2 * Hin + gh) * Win + gw) * 128 + c * 16) : 0);
                    CPASYNC_Z(nxt + row * 128 + ((c ^ (row & 7)) << 4), src, ok ? 16 : 0);
                }
                CPCOMMIT();
            }
        }

        float acc[MTILES][NTILES][4];
        #pragma unroll
        for (int mt = 0; mt < MTILES; mt++)
            #pragma unroll
            for (int nt = 0; nt < NTILES; nt++)
                #pragma unroll
                for (int q = 0; q < 4; q++) acc[mt][nt][q] = 0.0f;

        // ---- FULLY UNROLLED mainloop: 9 taps x 4 ks straight-line (ptxas pipelines
        //      next-tap LDSMs under current-tap MMAs; all addressing constant-folds) ----
        const uint32_t nrow0 = (uint32_t)(wn * 32) + bRow0;
        const uint32_t xb    = nrow0 & 7;
        const uint32_t bBase = sb + BOFF + nrow0 * 128;
        #pragma unroll
        for (int tap = 0; tap < 9; tap++) {
            const int dy = tap / 3, dx = tap % 3;
            const uint32_t rowA0 = (uint32_t)((wmr + dy) * PC + dx + wmc) + aLaneRow;
            const uint32_t aTap  = cur + rowA0 * 128;
            const uint32_t bTap  = bBase + tap * (NT * 128);
            const uint32_t xa    = rowA0 & 7;
            #pragma unroll
            for (int ks = 0; ks < 4; ks++) {
                const uint32_t aAddr = aTap + (((2 * ks + hiA) ^ xa) << 4);
                const uint32_t bAddr = bTap + (((2 * ks + hiB) ^ xb) << 4);
                uint32_t aF[MTILES][4], bF[8];
                #pragma unroll
                for (int mt = 0; mt < MTILES; mt++) LDSM4(aF[mt], aAddr + mt * 2048);
                #pragma unroll
                for (int p = 0; p < 2; p++) LDSM4(&bF[4 * p], bAddr + p * 2048);
                #pragma unroll
                for (int mt = 0; mt < MTILES; mt++)
                    #pragma unroll
                    for (int nt = 0; nt < NTILES; nt++) MMAH(acc[mt][nt], aF[mt], &bF[2 * nt]);
            }
        }
        __syncthreads();

        // ---- stage (n, m) fp32 + bias into the CONSUMED patch buffer ----
        float* st = (float*)(smem + ibuf * PB);
        #pragma unroll
        for (int mt = 0; mt < MTILES; mt++)
            #pragma unroll
            for (int nt = 0; nt < NTILES; nt++) {
                int nl = wn * 32 + nt * 8 + (lane & 3) * 2;
                int m  = wm * 32 + mt * 16 + (lane >> 2);
                float bv0, bv1;
                if (CONV1) {
                    int g = nl >> 4, cc = nl & 15;
                    int oc0 = g * 64 + cchx * 16 + cc;
                    bv0 = __ldg(&bias[oc0]);
                    bv1 = __ldg(&bias[oc0 + 1]);
                } else {
                    bv0 = __ldg(&bias[nl]);
                    bv1 = __ldg(&bias[nl + 1]);
                }
                st[(nl + 0) * STP + m]     = acc[mt][nt][0] + bv0;
                st[(nl + 1) * STP + m]     = acc[mt][nt][1] + bv1;
                st[(nl + 0) * STP + m + 8] = acc[mt][nt][2] + bv0;
                st[(nl + 1) * STP + m + 8] = acc[mt][nt][3] + bv1;
            }
        __syncthreads();

        if (CONV1) {
            // wavelet mix -> fp16 up NHWC. 512 items: m(256) x oct(2) ; channels cc = oct*8+j
            int m = tid >> 1, oct = tid & 1;
            int mr = m >> 7, mc = m & 127;
            float vll[8], vlh[8], vhl[8], vhh[8];
            #pragma unroll
            for (int j = 0; j < 8; j++) {
                int cc = oct * 8 + j;
                vll[j] = st[(0 * 16 + cc) * STP + m];
                vlh[j] = st[(1 * 16 + cc) * STP + m];
                vhl[j] = st[(2 * 16 + cc) * STP + m];
                vhh[j] = st[(3 * 16 + cc) * STP + m];
            }
            HF8 q[4];
            #pragma unroll
            for (int j = 0; j < 8; j++) {
                float ee = 0.5f * (vll[j] + vlh[j] + vhl[j] + vhh[j]);
                float eo = 0.5f * (vll[j] - vlh[j] + vhl[j] - vhh[j]);
                float oe = 0.5f * (vll[j] + vlh[j] - vhl[j] - vhh[j]);
                float oo = 0.5f * (vll[j] - vlh[j] - vhl[j] + vhh[j]);
                q[0].h[j] = __float2half_rn(ee);
                q[1].h[j] = __float2half_rn(eo);
                q[2].h[j] = __float2half_rn(oe);
                q[3].h[j] = __float2half_rn(oo);
            }
            int ccb = cchx * 16 + oct * 8;
            #pragma unroll
            for (int p = 0; p < 4; p++) {
                int dyp = p >> 1, dxp = p & 1;
                size_t px = (((size_t)b * H2 + 2 * (h0 + mr) + dyp) * W2 + 2 * mc + dxp) * 64;
                *(uint4*)&up[px + ccb] = q[p].v;
            }
        } else {
            for (int i = tid; i < 64 * 256; i += NTHREADS) {
                int n = i >> 8, m = i & 255;
                out[((size_t)(b * 64 + n) * H2 + h0 + (m >> 7)) * W2 + w0 + (m & 127)]
                    = st[n * STP + m];
            }
        }
    }
}

// ---------------- launch ----------------
extern "C" void kernel_launch(void* const* d_in, const int* in_sizes, int n_in,
                              void* d_out, int out_size)
{
    const float* x      = (const float*)d_in[0];
    const float* w_pre  = (const float*)d_in[1];
    const float* b_pre  = (const float*)d_in[2];
    const float* w_post = (const float*)d_in[3];
    const float* b_post = (const float*)d_in[4];
    float* out = (float*)d_out;

    __half *xt, *up, *wt1, *wt2;
    cudaGetSymbolAddress((void**)&xt,  g_xt);
    cudaGetSymbolAddress((void**)&up,  g_up);
    cudaGetSymbolAddress((void**)&wt1, g_wt1);
    cudaGetSymbolAddress((void**)&wt2, g_wt2);

    const int smemB = 206848;   // 2 patches (133,120) + B (73,728)
    cudaFuncSetAttribute(gemm_conv<true>,  cudaFuncAttributeMaxDynamicSharedMemorySize, smemB);
    cudaFuncSetAttribute(gemm_conv<false>, cudaFuncAttributeMaxDynamicSharedMemorySize, smemB);

    prep_x<<<dim3(4, 128, 16), 256>>>(x, xt);
    prep_w<<<(9 * 256 * 64 + 255) / 256, 256>>>(w_pre, wt1, 256, 1);
    prep_w<<<(9 * 64 * 64 + 255) / 256, 256>>>(w_post, wt2, 64, 0);

    gemm_conv<true><<<NSM, NTHREADS, smemB>>>(xt, wt1, b_pre, nullptr, up);
    gemm_conv<false><<<NSM, NTHREADS, smemB>>>(up, wt2, b_post, out, nullptr);
}